// round 1
// baseline (speedup 1.0000x reference)
#include <cuda_runtime.h>
#include <cuda_bf16.h>
#include <math.h>

// Problem constants
#define Bq   4
#define Tt   2048
#define Dd   1024
#define Hh   16
#define QKd  64
#define Mrows (Bq*Tt)          // 8192
#define HD   (Hh*QKd)          // 1024

// Scratch (device globals — allocation-free rule)
__device__ float g_qh[(size_t)Mrows*HD];
__device__ float g_kh[(size_t)Mrows*HD];
__device__ float g_vh[(size_t)Mrows*HD];
__device__ float g_at[(size_t)Mrows*HD];

// ---------------------------------------------------------------------------
// SGEMM with bias: C[M,N] = A[M,K] @ W[K,N] + bias[N]
// 128x128 tile, BK=8, 256 threads, 8x8 microtile (split 4+4 to avoid conflicts)
// ---------------------------------------------------------------------------
#define BM 128
#define BN 128
#define BK 8

__global__ void __launch_bounds__(256)
sgemm_bias(const float* __restrict__ A, const float* __restrict__ W,
           const float* __restrict__ bias, float* __restrict__ C,
           int M, int N, int K)
{
    __shared__ float As[BK][BM];
    __shared__ float Bs[BK][BN];

    const int tid = threadIdx.x;
    const int tx  = tid & 15;
    const int ty  = tid >> 4;
    const int bm  = blockIdx.y;
    const int bn  = blockIdx.x;

    // global load assignments
    const int arow = tid >> 1;            // 0..127
    const int acol = (tid & 1) * 4;       // 0 or 4
    const int brow = tid >> 5;            // 0..7
    const int bcol = (tid & 31) * 4;      // 0..124

    const float* Aptr = A + (size_t)(bm*BM + arow)*K + acol;
    const float* Bptr = W + (size_t)brow*N + bn*BN + bcol;

    float acc[8][8];
    #pragma unroll
    for (int i = 0; i < 8; i++)
        #pragma unroll
        for (int j = 0; j < 8; j++) acc[i][j] = 0.f;

    float4 a_next = *(const float4*)Aptr;
    float4 b_next = *(const float4*)Bptr;

    for (int k0 = 0; k0 < K; k0 += BK) {
        As[acol+0][arow] = a_next.x;
        As[acol+1][arow] = a_next.y;
        As[acol+2][arow] = a_next.z;
        As[acol+3][arow] = a_next.w;
        *(float4*)&Bs[brow][bcol] = b_next;
        __syncthreads();

        if (k0 + BK < K) {
            a_next = *(const float4*)(Aptr + k0 + BK);
            b_next = *(const float4*)(Bptr + (size_t)(k0 + BK)*N);
        }

        #pragma unroll
        for (int kk = 0; kk < BK; kk++) {
            float4 a0 = *(const float4*)&As[kk][ty*4];
            float4 a1 = *(const float4*)&As[kk][ty*4 + 64];
            float4 b0 = *(const float4*)&Bs[kk][tx*4];
            float4 b1 = *(const float4*)&Bs[kk][tx*4 + 64];
            float av[8] = {a0.x,a0.y,a0.z,a0.w, a1.x,a1.y,a1.z,a1.w};
            float bv[8] = {b0.x,b0.y,b0.z,b0.w, b1.x,b1.y,b1.z,b1.w};
            #pragma unroll
            for (int i = 0; i < 8; i++)
                #pragma unroll
                for (int j = 0; j < 8; j++)
                    acc[i][j] += av[i]*bv[j];
        }
        __syncthreads();
    }

    // epilogue
    #pragma unroll
    for (int i = 0; i < 8; i++) {
        int row = bm*BM + ((i < 4) ? (ty*4 + i) : (64 + ty*4 + i - 4));
        #pragma unroll
        for (int ch = 0; ch < 2; ch++) {
            int col = bn*BN + ch*64 + tx*4;
            float4 o;
            o.x = acc[i][ch*4+0] + bias[col+0];
            o.y = acc[i][ch*4+1] + bias[col+1];
            o.z = acc[i][ch*4+2] + bias[col+2];
            o.w = acc[i][ch*4+3] + bias[col+3];
            *(float4*)&C[(size_t)row*N + col] = o;
        }
    }
}

// ---------------------------------------------------------------------------
// RMSNorm (per 64-dim head) + RoPE, in place. One warp per (token, head).
// ---------------------------------------------------------------------------
__global__ void __launch_bounds__(256)
rms_rope(float* __restrict__ X, const float* __restrict__ scale,
         const int* __restrict__ pos, int total /* B*T*H */)
{
    int warp = (blockIdx.x * blockDim.x + threadIdx.x) >> 5;
    int lane = threadIdx.x & 31;
    if (warp >= total) return;

    float* x = X + (size_t)warp * QKd;
    float x1 = x[lane];
    float x2 = x[lane + 32];

    float ss = x1*x1 + x2*x2;
    #pragma unroll
    for (int off = 16; off; off >>= 1)
        ss += __shfl_xor_sync(0xffffffffu, ss, off);

    float rs = rsqrtf(ss * (1.0f/64.0f) + 1e-6f);
    float y1 = x1 * rs * (1.0f + scale[lane]);
    float y2 = x2 * rs * (1.0f + scale[lane + 32]);

    int token = warp >> 4;                       // / H
    float p  = (float)pos[token];
    float ts = powf(10000.0f, (float)lane * (1.0f/32.0f));
    float sv, cv;
    sincosf(p / ts, &sv, &cv);

    x[lane]      = y1*cv - y2*sv;
    x[lane + 32] = y2*cv + y1*sv;
}

// ---------------------------------------------------------------------------
// Flash attention, fp32, causal. 64 queries x 64 keys per tile, d=64.
// 256 threads; 4x4 microtile on the 64x64 S/O tiles. Online softmax.
// Layout of qh/kh/vh: (B, T, H, QK) row-major -> token stride = H*QK = 1024.
// ---------------------------------------------------------------------------
#define FLD 68   // padded smem row length

__global__ void __launch_bounds__(256)
flash_attn(const float* __restrict__ Qx, const float* __restrict__ Kx,
           const float* __restrict__ Vx, const float* __restrict__ hs,
           float* __restrict__ O)
{
    extern __shared__ float sm[];
    float* Qs = sm;                 // [d][row]  (transposed), 64 x FLD
    float* Ks = sm + 64*FLD;        // [d][col]  (transposed)
    float* Vs = sm + 2*64*FLD;      // [k][d]    (natural)
    float* Ps = sm + 3*64*FLD;      // [row][col]

    const int tid = threadIdx.x;
    const int tx  = tid & 15;
    const int ty  = tid >> 4;
    const int lr  = tid >> 4;       // 0..15 (row group for loads)
    const int ld  = (tid & 15) * 4; // 0..60 (dim group for loads)

    const int bh = blockIdx.y;
    const int b  = bh >> 4;
    const int h  = bh & 15;
    const int qt = gridDim.x - 1 - blockIdx.x;   // heavy tiles first

    const size_t base = ((size_t)b * Tt * Hh + h) * QKd;   // + t*1024 + d
    const float scale = 0.125f;    // 1/sqrt(64), folded into Q

    // load Q tile (transposed, pre-scaled)
    #pragma unroll
    for (int r = 0; r < 4; r++) {
        int row = lr + r*16;
        float4 v = *(const float4*)&Qx[base + (size_t)(qt*64 + row)*HD + ld];
        Qs[(ld+0)*FLD + row] = v.x * scale;
        Qs[(ld+1)*FLD + row] = v.y * scale;
        Qs[(ld+2)*FLD + row] = v.z * scale;
        Qs[(ld+3)*FLD + row] = v.w * scale;
    }

    float acc[4][4];
    float m[4], l[4];
    #pragma unroll
    for (int i = 0; i < 4; i++) {
        m[i] = -1e30f; l[i] = 0.f;
        #pragma unroll
        for (int j = 0; j < 4; j++) acc[i][j] = 0.f;
    }

    for (int kt = 0; kt <= qt; kt++) {
        // load K (transposed) and V (natural)
        #pragma unroll
        for (int r = 0; r < 4; r++) {
            int row = lr + r*16;
            size_t g = base + (size_t)(kt*64 + row)*HD + ld;
            float4 kv = *(const float4*)&Kx[g];
            Ks[(ld+0)*FLD + row] = kv.x;
            Ks[(ld+1)*FLD + row] = kv.y;
            Ks[(ld+2)*FLD + row] = kv.z;
            Ks[(ld+3)*FLD + row] = kv.w;
            float4 vv = *(const float4*)&Vx[g];
            *(float4*)&Vs[row*FLD + ld] = vv;
        }
        __syncthreads();

        // S = Q K^T (scaled)
        float s[4][4];
        #pragma unroll
        for (int i = 0; i < 4; i++)
            #pragma unroll
            for (int j = 0; j < 4; j++) s[i][j] = 0.f;

        #pragma unroll 8
        for (int kk = 0; kk < 64; kk++) {
            float4 qv = *(const float4*)&Qs[kk*FLD + ty*4];
            float4 kv = *(const float4*)&Ks[kk*FLD + tx*4];
            float qa[4] = {qv.x,qv.y,qv.z,qv.w};
            float ka[4] = {kv.x,kv.y,kv.z,kv.w};
            #pragma unroll
            for (int i = 0; i < 4; i++)
                #pragma unroll
                for (int j = 0; j < 4; j++)
                    s[i][j] += qa[i]*ka[j];
        }

        // causal mask on the diagonal tile
        if (kt == qt) {
            #pragma unroll
            for (int i = 0; i < 4; i++)
                #pragma unroll
                for (int j = 0; j < 4; j++)
                    if (tx*4 + j > ty*4 + i) s[i][j] = -1e30f;
        }

        // online softmax update (per row; replicated across the 16 tx lanes)
        #pragma unroll
        for (int i = 0; i < 4; i++) {
            float rmax = fmaxf(fmaxf(s[i][0], s[i][1]), fmaxf(s[i][2], s[i][3]));
            #pragma unroll
            for (int off = 8; off; off >>= 1)
                rmax = fmaxf(rmax, __shfl_xor_sync(0xffffffffu, rmax, off));
            float mnew = fmaxf(m[i], rmax);
            float corr = expf(m[i] - mnew);
            float psum = 0.f;
            #pragma unroll
            for (int j = 0; j < 4; j++) {
                s[i][j] = expf(s[i][j] - mnew);
                psum += s[i][j];
            }
            #pragma unroll
            for (int off = 8; off; off >>= 1)
                psum += __shfl_xor_sync(0xffffffffu, psum, off);
            l[i] = l[i]*corr + psum;
            m[i] = mnew;
            #pragma unroll
            for (int j = 0; j < 4; j++) acc[i][j] *= corr;
            *(float4*)&Ps[(ty*4 + i)*FLD + tx*4] =
                make_float4(s[i][0], s[i][1], s[i][2], s[i][3]);
        }
        __syncthreads();

        // O += P @ V
        #pragma unroll 8
        for (int kk = 0; kk < 64; kk++) {
            float4 vv = *(const float4*)&Vs[kk*FLD + tx*4];
            #pragma unroll
            for (int i = 0; i < 4; i++) {
                float p = Ps[(ty*4 + i)*FLD + kk];
                acc[i][0] += p*vv.x;
                acc[i][1] += p*vv.y;
                acc[i][2] += p*vv.z;
                acc[i][3] += p*vv.w;
            }
        }
        __syncthreads();
    }

    // epilogue: normalize, apply (1 + head_scale[h]), write
    float hsc = 1.0f + hs[h];
    #pragma unroll
    for (int i = 0; i < 4; i++) {
        float inv = hsc / l[i];
        int row = qt*64 + ty*4 + i;
        float4 o;
        o.x = acc[i][0]*inv;
        o.y = acc[i][1]*inv;
        o.z = acc[i][2]*inv;
        o.w = acc[i][3]*inv;
        *(float4*)&O[base + (size_t)row*HD + tx*4] = o;
    }
}

// ---------------------------------------------------------------------------
// launch
// ---------------------------------------------------------------------------
extern "C" void kernel_launch(void* const* d_in, const int* in_sizes, int n_in,
                              void* d_out, int out_size)
{
    const float* q    = (const float*)d_in[0];
    const float* kv   = (const float*)d_in[1];
    // d_in[2] = mask (causal tril; implemented analytically, not read)
    const int*   qpos = (const int*)d_in[3];
    const int*   kpos = (const int*)d_in[4];
    const float* Wq   = (const float*)d_in[5];
    const float* bq   = (const float*)d_in[6];
    const float* Wk   = (const float*)d_in[7];
    const float* bk   = (const float*)d_in[8];
    const float* Wv   = (const float*)d_in[9];
    const float* bv   = (const float*)d_in[10];
    const float* qsc  = (const float*)d_in[11];
    const float* ksc  = (const float*)d_in[12];
    const float* hsc  = (const float*)d_in[13];
    const float* Wo   = (const float*)d_in[14];
    const float* bo   = (const float*)d_in[15];
    float* out = (float*)d_out;

    float *qh, *kh, *vh, *at;
    cudaGetSymbolAddress((void**)&qh, g_qh);
    cudaGetSymbolAddress((void**)&kh, g_kh);
    cudaGetSymbolAddress((void**)&vh, g_vh);
    cudaGetSymbolAddress((void**)&at, g_at);

    dim3 gg(HD/BN, Mrows/BM);   // (8, 64)

    sgemm_bias<<<gg, 256>>>(q,  Wq, bq, qh, Mrows, HD, Dd);
    sgemm_bias<<<gg, 256>>>(kv, Wk, bk, kh, Mrows, HD, Dd);
    sgemm_bias<<<gg, 256>>>(kv, Wv, bv, vh, Mrows, HD, Dd);

    int total_th = Bq*Tt*Hh;          // 131072 warps of work
    rms_rope<<<total_th/8, 256>>>(qh, qsc, qpos, total_th);
    rms_rope<<<total_th/8, 256>>>(kh, ksc, kpos, total_th);

    int smem = 4 * 64 * FLD * (int)sizeof(float);   // 69632 B
    cudaFuncSetAttribute(flash_attn, cudaFuncAttributeMaxDynamicSharedMemorySize, smem);
    flash_attn<<<dim3(Tt/64, Bq*Hh), 256, smem>>>(qh, kh, vh, hsc, at);

    sgemm_bias<<<gg, 256>>>(at, Wo, bo, out, Mrows, Dd, HD);
}

// round 3
// speedup vs baseline: 1.5178x; 1.5178x over previous
#include <cuda_runtime.h>
#include <cuda_bf16.h>
#include <math.h>
#include <stdint.h>

// Problem constants
#define Bq   4
#define Tt   2048
#define Dd   1024
#define Hh   16
#define QKd  64
#define Mrows (Bq*Tt)          // 8192
#define HD   (Hh*QKd)          // 1024
#define GK   1024              // K for every GEMM here

// Scratch (device globals — allocation-free rule)
__device__ float g_qh[(size_t)Mrows*HD];
__device__ float g_kh[(size_t)Mrows*HD];
__device__ float g_vh[(size_t)Mrows*HD];
__device__ float g_at[(size_t)Mrows*HD];
__device__ float g_wt[4][(size_t)GK*HD];   // transposed weights

// ===========================================================================
// helpers
// ===========================================================================
__device__ __forceinline__ uint32_t smem_u32(const void* p) {
    uint32_t a;
    asm("{ .reg .u64 t; cvta.to.shared.u64 t, %1; cvt.u32.u64 %0, t; }"
        : "=r"(a) : "l"(p));
    return a;
}

__device__ __forceinline__ uint32_t f2tf32(float x) {
    uint32_t r;
    asm("cvt.rna.tf32.f32 %0, %1;" : "=r"(r) : "f"(x));
    return r;
}

#define CP_ASYNC16(dst_u32, src_ptr) \
    asm volatile("cp.async.cg.shared.global [%0], [%1], 16;" \
                 :: "r"(dst_u32), "l"(src_ptr) : "memory")
#define CP_COMMIT() asm volatile("cp.async.commit_group;" ::: "memory")
#define CP_WAIT1()  asm volatile("cp.async.wait_group 1;" ::: "memory")
#define CP_WAIT0()  asm volatile("cp.async.wait_group 0;" ::: "memory")

__device__ __forceinline__ void mma_tf32(float* c, const uint32_t* a, const uint32_t* b) {
    asm volatile(
        "mma.sync.aligned.m16n8k8.row.col.f32.tf32.tf32.f32 "
        "{%0,%1,%2,%3}, {%4,%5,%6,%7}, {%8,%9}, {%0,%1,%2,%3};"
        : "+f"(c[0]), "+f"(c[1]), "+f"(c[2]), "+f"(c[3])
        : "r"(a[0]), "r"(a[1]), "r"(a[2]), "r"(a[3]), "r"(b[0]), "r"(b[1]));
}

// ===========================================================================
// 1024x1024 transpose (weights -> K-major B operand)
// ===========================================================================
__global__ void __launch_bounds__(256)
transpose1024(const float* __restrict__ in, float* __restrict__ out)
{
    __shared__ float t[32][33];
    int bx = blockIdx.x * 32, by = blockIdx.y * 32;
    #pragma unroll
    for (int i = 0; i < 32; i += 8)
        t[threadIdx.y + i][threadIdx.x] = in[(size_t)(by + threadIdx.y + i) * 1024 + bx + threadIdx.x];
    __syncthreads();
    #pragma unroll
    for (int i = 0; i < 32; i += 8)
        out[(size_t)(bx + threadIdx.y + i) * 1024 + by + threadIdx.x] = t[threadIdx.x][threadIdx.y + i];
}

// ===========================================================================
// tf32 mma.sync GEMM: C[8192,N] = A[8192,1024] @ BT[N,1024]^T + bias
// BT is K-major (row n = W[:, n]).
// CTA 128x128, BK=32, 8 warps (4Mx2N), warp tile 32x64 (2x8 m16n8k8),
// cp.async double-buffered. Smem layout [128][36] (pad 4) per operand/stage.
// ===========================================================================
#define LDW 36                    // padded row length (floats)
#define STG_FLOATS (128*LDW)      // per operand per stage
#define GEMM_SMEM  (4*STG_FLOATS*4)  // 2 ops x 2 stages x 18432B = 73728

__device__ __forceinline__ void stage_load(uint32_t sdst, const float* __restrict__ gsrc,
                                           int tid)
{
    #pragma unroll
    for (int it = 0; it < 4; it++) {
        int idx = tid + it * 256;
        int r = idx >> 3, f = idx & 7;
        CP_ASYNC16(sdst + (r * LDW + f * 4) * 4, gsrc + (size_t)r * GK + f * 4);
    }
}

__global__ void __launch_bounds__(256, 2)
gemm_tf32(const float* __restrict__ A, const float* __restrict__ BT,
          const float* __restrict__ bias, float* __restrict__ C, int N)
{
    extern __shared__ float sm[];
    float* smA = sm;                     // [2][128][36]
    float* smB = sm + 2 * STG_FLOATS;    // [2][128][36]
    const uint32_t sA32 = smem_u32(smA);
    const uint32_t sB32 = smem_u32(smB);

    const int tid  = threadIdx.x;
    const int wid  = tid >> 5;
    const int lane = tid & 31;
    const int g    = lane >> 2;     // 0..7
    const int tg   = lane & 3;      // 0..3
    const int wm   = wid & 3;       // M block of 32
    const int wn   = wid >> 2;      // N block of 64
    const int bm   = blockIdx.y, bn = blockIdx.x;

    const float* gA = A  + (size_t)(bm * 128) * GK;
    const float* gB = BT + (size_t)(bn * 128) * GK;

    float acc[2][8][4];
    #pragma unroll
    for (int mt = 0; mt < 2; mt++)
        #pragma unroll
        for (int j = 0; j < 8; j++)
            #pragma unroll
            for (int r = 0; r < 4; r++) acc[mt][j][r] = 0.f;

    const int NC = GK / 32;   // 32 chunks

    // prologue: chunks 0,1
    stage_load(sA32, gA + 0, tid);
    stage_load(sB32, gB + 0, tid);
    CP_COMMIT();
    stage_load(sA32 + STG_FLOATS * 4, gA + 32, tid);
    stage_load(sB32 + STG_FLOATS * 4, gB + 32, tid);
    CP_COMMIT();

    for (int c = 0; c < NC; c++) {
        if (c + 2 < NC) CP_WAIT1(); else CP_WAIT0();
        __syncthreads();

        const int s = c & 1;
        const float* as = smA + s * STG_FLOATS;
        const float* bs = smB + s * STG_FLOATS;

        #pragma unroll
        for (int ks = 0; ks < 4; ks++) {
            const int k0 = ks * 8 + tg;
            uint32_t afr[2][4], bfr[8][2];
            #pragma unroll
            for (int mt = 0; mt < 2; mt++) {
                int m0 = wm * 32 + mt * 16 + g;
                afr[mt][0] = f2tf32(as[m0 * LDW + k0]);
                afr[mt][1] = f2tf32(as[(m0 + 8) * LDW + k0]);
                afr[mt][2] = f2tf32(as[m0 * LDW + k0 + 4]);
                afr[mt][3] = f2tf32(as[(m0 + 8) * LDW + k0 + 4]);
            }
            #pragma unroll
            for (int j = 0; j < 8; j++) {
                int n0 = wn * 64 + j * 8 + g;
                bfr[j][0] = f2tf32(bs[n0 * LDW + k0]);
                bfr[j][1] = f2tf32(bs[n0 * LDW + k0 + 4]);
            }
            #pragma unroll
            for (int mt = 0; mt < 2; mt++)
                #pragma unroll
                for (int j = 0; j < 8; j++)
                    mma_tf32(acc[mt][j], afr[mt], bfr[j]);
        }
        __syncthreads();

        if (c + 2 < NC) {
            stage_load(sA32 + s * STG_FLOATS * 4, gA + (c + 2) * 32, tid);
            stage_load(sB32 + s * STG_FLOATS * 4, gB + (c + 2) * 32, tid);
            CP_COMMIT();
        }
    }

    // epilogue
    #pragma unroll
    for (int mt = 0; mt < 2; mt++) {
        #pragma unroll
        for (int rr = 0; rr < 2; rr++) {
            int row = bm * 128 + wm * 32 + mt * 16 + g + rr * 8;
            float* Cp = C + (size_t)row * N + bn * 128 + wn * 64;
            const float* bp = bias + bn * 128 + wn * 64;
            #pragma unroll
            for (int j = 0; j < 8; j++) {
                int col = j * 8 + 2 * tg;
                float2 o;
                o.x = acc[mt][j][rr * 2 + 0] + bp[col];
                o.y = acc[mt][j][rr * 2 + 1] + bp[col + 1];
                *(float2*)(Cp + col) = o;
            }
        }
    }
}

// ---------------------------------------------------------------------------
// RMSNorm (per 64-dim head) + RoPE, in place. One warp per (token, head).
// ---------------------------------------------------------------------------
__global__ void __launch_bounds__(256)
rms_rope(float* __restrict__ X, const float* __restrict__ scale,
         const int* __restrict__ pos, int total /* B*T*H */)
{
    int warp = (blockIdx.x * blockDim.x + threadIdx.x) >> 5;
    int lane = threadIdx.x & 31;
    if (warp >= total) return;

    float* x = X + (size_t)warp * QKd;
    float x1 = x[lane];
    float x2 = x[lane + 32];

    float ss = x1*x1 + x2*x2;
    #pragma unroll
    for (int off = 16; off; off >>= 1)
        ss += __shfl_xor_sync(0xffffffffu, ss, off);

    float rs = rsqrtf(ss * (1.0f/64.0f) + 1e-6f);
    float y1 = x1 * rs * (1.0f + scale[lane]);
    float y2 = x2 * rs * (1.0f + scale[lane + 32]);

    int token = warp >> 4;                       // / H
    float p  = (float)pos[token];
    float ts = powf(10000.0f, (float)lane * (1.0f/32.0f));
    float sv, cv;
    sincosf(p / ts, &sv, &cv);

    x[lane]      = y1*cv - y2*sv;
    x[lane + 32] = y2*cv + y1*sv;
}

// ---------------------------------------------------------------------------
// Flash attention, fp32, causal. 64 queries x 64 keys per tile, d=64.
// ---------------------------------------------------------------------------
#define FLD 68   // padded smem row length

__global__ void __launch_bounds__(256)
flash_attn(const float* __restrict__ Qx, const float* __restrict__ Kx,
           const float* __restrict__ Vx, const float* __restrict__ hs,
           float* __restrict__ O)
{
    extern __shared__ float smf[];
    float* Qs = smf;                 // [d][row]  (transposed), 64 x FLD
    float* Ks = smf + 64*FLD;        // [d][col]  (transposed)
    float* Vs = smf + 2*64*FLD;      // [k][d]    (natural)
    float* Ps = smf + 3*64*FLD;      // [row][col]

    const int tid = threadIdx.x;
    const int tx  = tid & 15;
    const int ty  = tid >> 4;
    const int lr  = tid >> 4;
    const int ld  = (tid & 15) * 4;

    const int bh = blockIdx.y;
    const int b  = bh >> 4;
    const int h  = bh & 15;
    const int qt = gridDim.x - 1 - blockIdx.x;

    const size_t base = ((size_t)b * Tt * Hh + h) * QKd;
    const float scale = 0.125f;

    #pragma unroll
    for (int r = 0; r < 4; r++) {
        int row = lr + r*16;
        float4 v = *(const float4*)&Qx[base + (size_t)(qt*64 + row)*HD + ld];
        Qs[(ld+0)*FLD + row] = v.x * scale;
        Qs[(ld+1)*FLD + row] = v.y * scale;
        Qs[(ld+2)*FLD + row] = v.z * scale;
        Qs[(ld+3)*FLD + row] = v.w * scale;
    }

    float acc[4][4];
    float m[4], l[4];
    #pragma unroll
    for (int i = 0; i < 4; i++) {
        m[i] = -1e30f; l[i] = 0.f;
        #pragma unroll
        for (int j = 0; j < 4; j++) acc[i][j] = 0.f;
    }

    for (int kt = 0; kt <= qt; kt++) {
        #pragma unroll
        for (int r = 0; r < 4; r++) {
            int row = lr + r*16;
            size_t gidx = base + (size_t)(kt*64 + row)*HD + ld;
            float4 kvv = *(const float4*)&Kx[gidx];
            Ks[(ld+0)*FLD + row] = kvv.x;
            Ks[(ld+1)*FLD + row] = kvv.y;
            Ks[(ld+2)*FLD + row] = kvv.z;
            Ks[(ld+3)*FLD + row] = kvv.w;
            float4 vv = *(const float4*)&Vx[gidx];
            *(float4*)&Vs[row*FLD + ld] = vv;
        }
        __syncthreads();

        float s[4][4];
        #pragma unroll
        for (int i = 0; i < 4; i++)
            #pragma unroll
            for (int j = 0; j < 4; j++) s[i][j] = 0.f;

        #pragma unroll 8
        for (int kk = 0; kk < 64; kk++) {
            float4 qv = *(const float4*)&Qs[kk*FLD + ty*4];
            float4 kv = *(const float4*)&Ks[kk*FLD + tx*4];
            float qa[4] = {qv.x,qv.y,qv.z,qv.w};
            float ka[4] = {kv.x,kv.y,kv.z,kv.w};
            #pragma unroll
            for (int i = 0; i < 4; i++)
                #pragma unroll
                for (int j = 0; j < 4; j++)
                    s[i][j] += qa[i]*ka[j];
        }

        if (kt == qt) {
            #pragma unroll
            for (int i = 0; i < 4; i++)
                #pragma unroll
                for (int j = 0; j < 4; j++)
                    if (tx*4 + j > ty*4 + i) s[i][j] = -1e30f;
        }

        #pragma unroll
        for (int i = 0; i < 4; i++) {
            float rmax = fmaxf(fmaxf(s[i][0], s[i][1]), fmaxf(s[i][2], s[i][3]));
            #pragma unroll
            for (int off = 8; off; off >>= 1)
                rmax = fmaxf(rmax, __shfl_xor_sync(0xffffffffu, rmax, off));
            float mnew = fmaxf(m[i], rmax);
            float corr = expf(m[i] - mnew);
            float psum = 0.f;
            #pragma unroll
            for (int j = 0; j < 4; j++) {
                s[i][j] = expf(s[i][j] - mnew);
                psum += s[i][j];
            }
            #pragma unroll
            for (int off = 8; off; off >>= 1)
                psum += __shfl_xor_sync(0xffffffffu, psum, off);
            l[i] = l[i]*corr + psum;
            m[i] = mnew;
            #pragma unroll
            for (int j = 0; j < 4; j++) acc[i][j] *= corr;
            *(float4*)&Ps[(ty*4 + i)*FLD + tx*4] =
                make_float4(s[i][0], s[i][1], s[i][2], s[i][3]);
        }
        __syncthreads();

        #pragma unroll 8
        for (int kk = 0; kk < 64; kk++) {
            float4 vv = *(const float4*)&Vs[kk*FLD + tx*4];
            #pragma unroll
            for (int i = 0; i < 4; i++) {
                float p = Ps[(ty*4 + i)*FLD + kk];
                acc[i][0] += p*vv.x;
                acc[i][1] += p*vv.y;
                acc[i][2] += p*vv.z;
                acc[i][3] += p*vv.w;
            }
        }
        __syncthreads();
    }

    float hsc = 1.0f + hs[h];
    #pragma unroll
    for (int i = 0; i < 4; i++) {
        float inv = hsc / l[i];
        int row = qt*64 + ty*4 + i;
        float4 o;
        o.x = acc[i][0]*inv;
        o.y = acc[i][1]*inv;
        o.z = acc[i][2]*inv;
        o.w = acc[i][3]*inv;
        *(float4*)&O[base + (size_t)row*HD + tx*4] = o;
    }
}

// ---------------------------------------------------------------------------
// launch
// ---------------------------------------------------------------------------
extern "C" void kernel_launch(void* const* d_in, const int* in_sizes, int n_in,
                              void* d_out, int out_size)
{
    const float* q    = (const float*)d_in[0];
    const float* kv   = (const float*)d_in[1];
    const int*   qpos = (const int*)d_in[3];
    const int*   kpos = (const int*)d_in[4];
    const float* Wq   = (const float*)d_in[5];
    const float* bq   = (const float*)d_in[6];
    const float* Wk   = (const float*)d_in[7];
    const float* bk   = (const float*)d_in[8];
    const float* Wv   = (const float*)d_in[9];
    const float* bv   = (const float*)d_in[10];
    const float* qsc  = (const float*)d_in[11];
    const float* ksc  = (const float*)d_in[12];
    const float* hsc  = (const float*)d_in[13];
    const float* Wo   = (const float*)d_in[14];
    const float* bo   = (const float*)d_in[15];
    float* out = (float*)d_out;

    float *qh, *kh, *vh, *at, *wt;
    cudaGetSymbolAddress((void**)&qh, g_qh);
    cudaGetSymbolAddress((void**)&kh, g_kh);
    cudaGetSymbolAddress((void**)&vh, g_vh);
    cudaGetSymbolAddress((void**)&at, g_at);
    cudaGetSymbolAddress((void**)&wt, g_wt);
    float* WqT = wt;
    float* WkT = wt + (size_t)GK*HD;
    float* WvT = wt + 2*(size_t)GK*HD;
    float* WoT = wt + 3*(size_t)GK*HD;

    // transpose weights -> K-major B operands
    dim3 tb(32, 8), tg(32, 32);
    transpose1024<<<tg, tb>>>(Wq, WqT);
    transpose1024<<<tg, tb>>>(Wk, WkT);
    transpose1024<<<tg, tb>>>(Wv, WvT);
    transpose1024<<<tg, tb>>>(Wo, WoT);

    cudaFuncSetAttribute(gemm_tf32, cudaFuncAttributeMaxDynamicSharedMemorySize, GEMM_SMEM);
    cudaFuncSetAttribute(flash_attn, cudaFuncAttributeMaxDynamicSharedMemorySize,
                         4 * 64 * FLD * (int)sizeof(float));

    dim3 gg(HD/128, Mrows/128);   // (8, 64)
    gemm_tf32<<<gg, 256, GEMM_SMEM>>>(q,  WqT, bq, qh, HD);
    gemm_tf32<<<gg, 256, GEMM_SMEM>>>(kv, WkT, bk, kh, HD);
    gemm_tf32<<<gg, 256, GEMM_SMEM>>>(kv, WvT, bv, vh, HD);

    int total_th = Bq*Tt*Hh;
    rms_rope<<<total_th/8, 256>>>(qh, qsc, qpos, total_th);
    rms_rope<<<total_th/8, 256>>>(kh, ksc, kpos, total_th);

    int smem = 4 * 64 * FLD * (int)sizeof(float);   // 69632 B
    flash_attn<<<dim3(Tt/64, Bq*Hh), 256, smem>>>(qh, kh, vh, hsc, at);

    gemm_tf32<<<gg, 256, GEMM_SMEM>>>(at, WoT, bo, out, Dd);
}

// round 4
// speedup vs baseline: 2.7471x; 1.8099x over previous
#include <cuda_runtime.h>
#include <cuda_bf16.h>
#include <math.h>
#include <stdint.h>

// Problem constants
#define Bq   4
#define Tt   2048
#define Dd   1024
#define Hh   16
#define QKd  64
#define Mrows (Bq*Tt)          // 8192
#define HD   (Hh*QKd)          // 1024
#define GK   1024              // K for every GEMM here

// Scratch (device globals — allocation-free rule)
__device__ float g_qh[(size_t)Mrows*HD];
__device__ float g_kh[(size_t)Mrows*HD];
__device__ float g_vh[(size_t)Mrows*HD];
__device__ float g_at[(size_t)Mrows*HD];
__device__ float g_wt[4][(size_t)GK*HD];   // transposed weights

// ===========================================================================
// helpers
// ===========================================================================
__device__ __forceinline__ uint32_t smem_u32(const void* p) {
    uint32_t a;
    asm("{ .reg .u64 t; cvta.to.shared.u64 t, %1; cvt.u32.u64 %0, t; }"
        : "=r"(a) : "l"(p));
    return a;
}

__device__ __forceinline__ uint32_t f2tf32(float x) {
    uint32_t r;
    asm("cvt.rna.tf32.f32 %0, %1;" : "=r"(r) : "f"(x));
    return r;
}

#define CP_ASYNC16(dst_u32, src_ptr) \
    asm volatile("cp.async.cg.shared.global [%0], [%1], 16;" \
                 :: "r"(dst_u32), "l"(src_ptr) : "memory")
#define CP_COMMIT() asm volatile("cp.async.commit_group;" ::: "memory")
#define CP_WAIT1()  asm volatile("cp.async.wait_group 1;" ::: "memory")
#define CP_WAIT0()  asm volatile("cp.async.wait_group 0;" ::: "memory")

__device__ __forceinline__ void mma_tf32(float* c, const uint32_t* a, const uint32_t* b) {
    asm volatile(
        "mma.sync.aligned.m16n8k8.row.col.f32.tf32.tf32.f32 "
        "{%0,%1,%2,%3}, {%4,%5,%6,%7}, {%8,%9}, {%0,%1,%2,%3};"
        : "+f"(c[0]), "+f"(c[1]), "+f"(c[2]), "+f"(c[3])
        : "r"(a[0]), "r"(a[1]), "r"(a[2]), "r"(a[3]), "r"(b[0]), "r"(b[1]));
}

// ===========================================================================
// 1024x1024 transpose (weights -> K-major B operand)
// ===========================================================================
__global__ void __launch_bounds__(256)
transpose1024(const float* __restrict__ in, float* __restrict__ out)
{
    __shared__ float t[32][33];
    int bx = blockIdx.x * 32, by = blockIdx.y * 32;
    #pragma unroll
    for (int i = 0; i < 32; i += 8)
        t[threadIdx.y + i][threadIdx.x] = in[(size_t)(by + threadIdx.y + i) * 1024 + bx + threadIdx.x];
    __syncthreads();
    #pragma unroll
    for (int i = 0; i < 32; i += 8)
        out[(size_t)(bx + threadIdx.y + i) * 1024 + by + threadIdx.x] = t[threadIdx.x][threadIdx.y + i];
}

// ===========================================================================
// tf32 mma.sync GEMM: C[8192,N] = A[8192,1024] @ BT[N,1024]^T + bias
// ===========================================================================
#define LDW 36                    // padded row length (floats)
#define STG_FLOATS (128*LDW)      // per operand per stage
#define GEMM_SMEM  (4*STG_FLOATS*4)  // 73728

__device__ __forceinline__ void stage_load(uint32_t sdst, const float* __restrict__ gsrc,
                                           int tid)
{
    #pragma unroll
    for (int it = 0; it < 4; it++) {
        int idx = tid + it * 256;
        int r = idx >> 3, f = idx & 7;
        CP_ASYNC16(sdst + (r * LDW + f * 4) * 4, gsrc + (size_t)r * GK + f * 4);
    }
}

__global__ void __launch_bounds__(256, 2)
gemm_tf32(const float* __restrict__ A, const float* __restrict__ BT,
          const float* __restrict__ bias, float* __restrict__ C, int N)
{
    extern __shared__ float sm[];
    float* smA = sm;                     // [2][128][36]
    float* smB = sm + 2 * STG_FLOATS;    // [2][128][36]
    const uint32_t sA32 = smem_u32(smA);
    const uint32_t sB32 = smem_u32(smB);

    const int tid  = threadIdx.x;
    const int wid  = tid >> 5;
    const int lane = tid & 31;
    const int g    = lane >> 2;
    const int tg   = lane & 3;
    const int wm   = wid & 3;
    const int wn   = wid >> 2;
    const int bm   = blockIdx.y, bn = blockIdx.x;

    const float* gA = A  + (size_t)(bm * 128) * GK;
    const float* gB = BT + (size_t)(bn * 128) * GK;

    float acc[2][8][4];
    #pragma unroll
    for (int mt = 0; mt < 2; mt++)
        #pragma unroll
        for (int j = 0; j < 8; j++)
            #pragma unroll
            for (int r = 0; r < 4; r++) acc[mt][j][r] = 0.f;

    const int NC = GK / 32;

    stage_load(sA32, gA + 0, tid);
    stage_load(sB32, gB + 0, tid);
    CP_COMMIT();
    stage_load(sA32 + STG_FLOATS * 4, gA + 32, tid);
    stage_load(sB32 + STG_FLOATS * 4, gB + 32, tid);
    CP_COMMIT();

    for (int c = 0; c < NC; c++) {
        if (c + 2 < NC) CP_WAIT1(); else CP_WAIT0();
        __syncthreads();

        const int s = c & 1;
        const float* as = smA + s * STG_FLOATS;
        const float* bs = smB + s * STG_FLOATS;

        #pragma unroll
        for (int ks = 0; ks < 4; ks++) {
            const int k0 = ks * 8 + tg;
            uint32_t afr[2][4], bfr[8][2];
            #pragma unroll
            for (int mt = 0; mt < 2; mt++) {
                int m0 = wm * 32 + mt * 16 + g;
                afr[mt][0] = f2tf32(as[m0 * LDW + k0]);
                afr[mt][1] = f2tf32(as[(m0 + 8) * LDW + k0]);
                afr[mt][2] = f2tf32(as[m0 * LDW + k0 + 4]);
                afr[mt][3] = f2tf32(as[(m0 + 8) * LDW + k0 + 4]);
            }
            #pragma unroll
            for (int j = 0; j < 8; j++) {
                int n0 = wn * 64 + j * 8 + g;
                bfr[j][0] = f2tf32(bs[n0 * LDW + k0]);
                bfr[j][1] = f2tf32(bs[n0 * LDW + k0 + 4]);
            }
            #pragma unroll
            for (int mt = 0; mt < 2; mt++)
                #pragma unroll
                for (int j = 0; j < 8; j++)
                    mma_tf32(acc[mt][j], afr[mt], bfr[j]);
        }
        __syncthreads();

        if (c + 2 < NC) {
            stage_load(sA32 + s * STG_FLOATS * 4, gA + (c + 2) * 32, tid);
            stage_load(sB32 + s * STG_FLOATS * 4, gB + (c + 2) * 32, tid);
            CP_COMMIT();
        }
    }

    #pragma unroll
    for (int mt = 0; mt < 2; mt++) {
        #pragma unroll
        for (int rr = 0; rr < 2; rr++) {
            int row = bm * 128 + wm * 32 + mt * 16 + g + rr * 8;
            float* Cp = C + (size_t)row * N + bn * 128 + wn * 64;
            const float* bp = bias + bn * 128 + wn * 64;
            #pragma unroll
            for (int j = 0; j < 8; j++) {
                int col = j * 8 + 2 * tg;
                float2 o;
                o.x = acc[mt][j][rr * 2 + 0] + bp[col];
                o.y = acc[mt][j][rr * 2 + 1] + bp[col + 1];
                *(float2*)(Cp + col) = o;
            }
        }
    }
}

// ---------------------------------------------------------------------------
// RMSNorm (per 64-dim head) + RoPE, in place. One warp per (token, head).
// ---------------------------------------------------------------------------
__global__ void __launch_bounds__(256)
rms_rope(float* __restrict__ X, const float* __restrict__ scale,
         const int* __restrict__ pos, int total)
{
    int warp = (blockIdx.x * blockDim.x + threadIdx.x) >> 5;
    int lane = threadIdx.x & 31;
    if (warp >= total) return;

    float* x = X + (size_t)warp * QKd;
    float x1 = x[lane];
    float x2 = x[lane + 32];

    float ss = x1*x1 + x2*x2;
    #pragma unroll
    for (int off = 16; off; off >>= 1)
        ss += __shfl_xor_sync(0xffffffffu, ss, off);

    float rs = rsqrtf(ss * (1.0f/64.0f) + 1e-6f);
    float y1 = x1 * rs * (1.0f + scale[lane]);
    float y2 = x2 * rs * (1.0f + scale[lane + 32]);

    int token = warp >> 4;
    float p  = (float)pos[token];
    float ts = powf(10000.0f, (float)lane * (1.0f/32.0f));
    float sv, cv;
    sincosf(p / ts, &sv, &cv);

    x[lane]      = y1*cv - y2*sv;
    x[lane + 32] = y2*cv + y1*sv;
}

// ===========================================================================
// Flash attention with tf32 mma.sync. CTA: 128 q-rows, 8 warps (16 rows each),
// K/V tiles of 64 keys, cp.async double-buffered. Causal.
// Layout of qh/kh/vh: (B, T, H, QK) -> token stride = 1024.
// ===========================================================================
#define LDK 68                         // K tile row pitch (floats)
#define LDV 72                         // V tile row pitch (floats)
#define KSTG (64*LDK)                  // 4352 floats
#define VSTG (64*LDV)                  // 4608 floats
#define FA_SMEM ((2*KSTG + 2*VSTG)*4)  // 71680 B

__global__ void __launch_bounds__(256, 2)
flash_mma(const float* __restrict__ Qx, const float* __restrict__ Kx,
          const float* __restrict__ Vx, const float* __restrict__ hs,
          float* __restrict__ O)
{
    extern __shared__ float smf[];
    float* Kbuf = smf;                // [2][64][LDK]
    float* Vbuf = smf + 2*KSTG;       // [2][64][LDV]
    const uint32_t K32 = smem_u32(Kbuf);
    const uint32_t V32 = smem_u32(Vbuf);

    const int tid  = threadIdx.x;
    const int wid  = tid >> 5;
    const int lane = tid & 31;
    const int g    = lane >> 2;       // 0..7
    const int t    = lane & 3;        // 0..3

    const int bh = blockIdx.y;
    const int b  = bh >> 4;
    const int h  = bh & 15;
    const int qt = gridDim.x - 1 - blockIdx.x;   // heavy tiles first

    const size_t base = ((size_t)b * Tt * Hh + h) * QKd;
    const int row0 = qt * 128 + wid * 16;        // warp's first q row
    const int nkt  = 2 * qt + 2;

    // ---- load Q fragments once (A operand, pre-scaled by 1/8) ----
    uint32_t qa[8][4];
    {
        const float* Qp  = Qx + base + (size_t)(row0 + g) * HD;
        const float* Qp8 = Qp + (size_t)8 * HD;
        #pragma unroll
        for (int ks = 0; ks < 8; ks++) {
            int k0 = ks * 8 + t;
            qa[ks][0] = f2tf32(Qp [k0]     * 0.125f);
            qa[ks][1] = f2tf32(Qp8[k0]     * 0.125f);
            qa[ks][2] = f2tf32(Qp [k0 + 4] * 0.125f);
            qa[ks][3] = f2tf32(Qp8[k0 + 4] * 0.125f);
        }
    }

    // ---- cp.async loader for one K/V tile ----
    // 64 rows x 64 floats each; 256 threads x 4 float4 per operand.
    #define LOAD_KV(kt_, s_) do {                                            \
        int tok0 = (kt_) * 64;                                               \
        uint32_t kd = K32 + (s_) * KSTG * 4;                                 \
        uint32_t vd = V32 + (s_) * VSTG * 4;                                 \
        _Pragma("unroll")                                                    \
        for (int it = 0; it < 4; it++) {                                     \
            int idx = tid + it * 256;                                        \
            int j = idx >> 4, f = (idx & 15) * 4;                            \
            const float* ksrc = Kx + base + (size_t)(tok0 + j) * HD + f;     \
            const float* vsrc = Vx + base + (size_t)(tok0 + j) * HD + f;     \
            CP_ASYNC16(kd + (j * LDK + f) * 4, ksrc);                        \
            CP_ASYNC16(vd + (j * LDV + f) * 4, vsrc);                        \
        }                                                                    \
    } while (0)

    LOAD_KV(0, 0);
    CP_COMMIT();

    float oa[8][4];
    #pragma unroll
    for (int i = 0; i < 8; i++)
        #pragma unroll
        for (int r = 0; r < 4; r++) oa[i][r] = 0.f;
    float m0 = -1e30f, m1 = -1e30f, l0 = 0.f, l1 = 0.f;

    for (int kt = 0; kt < nkt; kt++) {
        CP_WAIT0();
        __syncthreads();
        if (kt + 1 < nkt) {
            LOAD_KV(kt + 1, (kt + 1) & 1);
            CP_COMMIT();
        }
        const float* Ks = Kbuf + (kt & 1) * KSTG;
        const float* Vs = Vbuf + (kt & 1) * VSTG;

        // ---- S = Q K^T ----
        float sa[8][4];
        #pragma unroll
        for (int j = 0; j < 8; j++)
            #pragma unroll
            for (int r = 0; r < 4; r++) sa[j][r] = 0.f;

        #pragma unroll
        for (int ks = 0; ks < 8; ks++) {
            int k0 = ks * 8 + t;
            uint32_t kb[8][2];
            #pragma unroll
            for (int nj = 0; nj < 8; nj++) {
                const float* kr = Ks + (nj * 8 + g) * LDK;
                kb[nj][0] = f2tf32(kr[k0]);
                kb[nj][1] = f2tf32(kr[k0 + 4]);
            }
            #pragma unroll
            for (int nj = 0; nj < 8; nj++)
                mma_tf32(sa[nj], qa[ks], kb[nj]);
        }

        // ---- causal mask ----
        if (kt * 64 + 63 > row0) {
            int r0g = row0 + g, r1g = row0 + 8 + g;
            #pragma unroll
            for (int j = 0; j < 8; j++) {
                int c0 = kt * 64 + j * 8 + 2 * t;
                if (c0     > r0g) sa[j][0] = -1e30f;
                if (c0 + 1 > r0g) sa[j][1] = -1e30f;
                if (c0     > r1g) sa[j][2] = -1e30f;
                if (c0 + 1 > r1g) sa[j][3] = -1e30f;
            }
        }

        // ---- online softmax (rows g and g+8, reduced over lane quad) ----
        float rmax0 = -1e30f, rmax1 = -1e30f;
        #pragma unroll
        for (int j = 0; j < 8; j++) {
            rmax0 = fmaxf(rmax0, fmaxf(sa[j][0], sa[j][1]));
            rmax1 = fmaxf(rmax1, fmaxf(sa[j][2], sa[j][3]));
        }
        rmax0 = fmaxf(rmax0, __shfl_xor_sync(0xffffffffu, rmax0, 1));
        rmax0 = fmaxf(rmax0, __shfl_xor_sync(0xffffffffu, rmax0, 2));
        rmax1 = fmaxf(rmax1, __shfl_xor_sync(0xffffffffu, rmax1, 1));
        rmax1 = fmaxf(rmax1, __shfl_xor_sync(0xffffffffu, rmax1, 2));

        float mn0 = fmaxf(m0, rmax0), mn1 = fmaxf(m1, rmax1);
        float corr0 = __expf(m0 - mn0), corr1 = __expf(m1 - mn1);
        m0 = mn0; m1 = mn1;

        float sum0 = 0.f, sum1 = 0.f;
        #pragma unroll
        for (int j = 0; j < 8; j++) {
            sa[j][0] = __expf(sa[j][0] - mn0);
            sa[j][1] = __expf(sa[j][1] - mn0);
            sa[j][2] = __expf(sa[j][2] - mn1);
            sa[j][3] = __expf(sa[j][3] - mn1);
            sum0 += sa[j][0] + sa[j][1];
            sum1 += sa[j][2] + sa[j][3];
        }
        sum0 += __shfl_xor_sync(0xffffffffu, sum0, 1);
        sum0 += __shfl_xor_sync(0xffffffffu, sum0, 2);
        sum1 += __shfl_xor_sync(0xffffffffu, sum1, 1);
        sum1 += __shfl_xor_sync(0xffffffffu, sum1, 2);
        l0 = l0 * corr0 + sum0;
        l1 = l1 * corr1 + sum1;

        #pragma unroll
        for (int i = 0; i < 8; i++) {
            oa[i][0] *= corr0; oa[i][1] *= corr0;
            oa[i][2] *= corr1; oa[i][3] *= corr1;
        }

        // ---- O += P V : convert P (C-layout) to A-layout via quad shuffles ----
        const int srcA = (lane & ~3) | (t >> 1);
        const int srcB = srcA + 2;
        const bool odd = t & 1;
        #pragma unroll
        for (int js = 0; js < 8; js++) {
            float u0 = __shfl_sync(0xffffffffu, sa[js][0], srcA);
            float u1 = __shfl_sync(0xffffffffu, sa[js][1], srcA);
            float u2 = __shfl_sync(0xffffffffu, sa[js][2], srcA);
            float u3 = __shfl_sync(0xffffffffu, sa[js][3], srcA);
            float w0 = __shfl_sync(0xffffffffu, sa[js][0], srcB);
            float w1 = __shfl_sync(0xffffffffu, sa[js][1], srcB);
            float w2 = __shfl_sync(0xffffffffu, sa[js][2], srcB);
            float w3 = __shfl_sync(0xffffffffu, sa[js][3], srcB);
            uint32_t pa[4];
            pa[0] = f2tf32(odd ? u1 : u0);
            pa[1] = f2tf32(odd ? u3 : u2);
            pa[2] = f2tf32(odd ? w1 : w0);
            pa[3] = f2tf32(odd ? w3 : w2);

            const float* vr0 = Vs + (js * 8 + t) * LDV;
            const float* vr4 = Vs + (js * 8 + t + 4) * LDV;
            #pragma unroll
            for (int nt = 0; nt < 8; nt++) {
                uint32_t vb[2];
                vb[0] = f2tf32(vr0[nt * 8 + g]);
                vb[1] = f2tf32(vr4[nt * 8 + g]);
                mma_tf32(oa[nt], pa, vb);
            }
        }
        __syncthreads();
    }

    // ---- epilogue ----
    float hsc = 1.0f + hs[h];
    float inv0 = hsc / l0, inv1 = hsc / l1;
    float* O0 = O + base + (size_t)(row0 + g) * HD;
    float* O1 = O + base + (size_t)(row0 + 8 + g) * HD;
    #pragma unroll
    for (int nt = 0; nt < 8; nt++) {
        int col = nt * 8 + 2 * t;
        float2 a, c;
        a.x = oa[nt][0] * inv0; a.y = oa[nt][1] * inv0;
        c.x = oa[nt][2] * inv1; c.y = oa[nt][3] * inv1;
        *(float2*)(O0 + col) = a;
        *(float2*)(O1 + col) = c;
    }
}

// ---------------------------------------------------------------------------
// launch
// ---------------------------------------------------------------------------
extern "C" void kernel_launch(void* const* d_in, const int* in_sizes, int n_in,
                              void* d_out, int out_size)
{
    const float* q    = (const float*)d_in[0];
    const float* kv   = (const float*)d_in[1];
    const int*   qpos = (const int*)d_in[3];
    const int*   kpos = (const int*)d_in[4];
    const float* Wq   = (const float*)d_in[5];
    const float* bq   = (const float*)d_in[6];
    const float* Wk   = (const float*)d_in[7];
    const float* bk   = (const float*)d_in[8];
    const float* Wv   = (const float*)d_in[9];
    const float* bv   = (const float*)d_in[10];
    const float* qsc  = (const float*)d_in[11];
    const float* ksc  = (const float*)d_in[12];
    const float* hsc  = (const float*)d_in[13];
    const float* Wo   = (const float*)d_in[14];
    const float* bo   = (const float*)d_in[15];
    float* out = (float*)d_out;

    float *qh, *kh, *vh, *at, *wt;
    cudaGetSymbolAddress((void**)&qh, g_qh);
    cudaGetSymbolAddress((void**)&kh, g_kh);
    cudaGetSymbolAddress((void**)&vh, g_vh);
    cudaGetSymbolAddress((void**)&at, g_at);
    cudaGetSymbolAddress((void**)&wt, g_wt);
    float* WqT = wt;
    float* WkT = wt + (size_t)GK*HD;
    float* WvT = wt + 2*(size_t)GK*HD;
    float* WoT = wt + 3*(size_t)GK*HD;

    dim3 tb(32, 8), tg(32, 32);
    transpose1024<<<tg, tb>>>(Wq, WqT);
    transpose1024<<<tg, tb>>>(Wk, WkT);
    transpose1024<<<tg, tb>>>(Wv, WvT);
    transpose1024<<<tg, tb>>>(Wo, WoT);

    cudaFuncSetAttribute(gemm_tf32, cudaFuncAttributeMaxDynamicSharedMemorySize, GEMM_SMEM);
    cudaFuncSetAttribute(flash_mma, cudaFuncAttributeMaxDynamicSharedMemorySize, FA_SMEM);

    dim3 gg(HD/128, Mrows/128);   // (8, 64)
    gemm_tf32<<<gg, 256, GEMM_SMEM>>>(q,  WqT, bq, qh, HD);
    gemm_tf32<<<gg, 256, GEMM_SMEM>>>(kv, WkT, bk, kh, HD);
    gemm_tf32<<<gg, 256, GEMM_SMEM>>>(kv, WvT, bv, vh, HD);

    int total_th = Bq*Tt*Hh;
    rms_rope<<<total_th/8, 256>>>(qh, qsc, qpos, total_th);
    rms_rope<<<total_th/8, 256>>>(kh, ksc, kpos, total_th);

    flash_mma<<<dim3(Tt/128, Bq*Hh), 256, FA_SMEM>>>(qh, kh, vh, hsc, at);

    gemm_tf32<<<gg, 256, GEMM_SMEM>>>(at, WoT, bo, out, Dd);
}

// round 5
// speedup vs baseline: 3.0401x; 1.1067x over previous
#include <cuda_runtime.h>
#include <cuda_bf16.h>
#include <math.h>
#include <stdint.h>

// Problem constants
#define Bq   4
#define Tt   2048
#define Dd   1024
#define Hh   16
#define QKd  64
#define Mrows (Bq*Tt)          // 8192
#define HD   (Hh*QKd)          // 1024
#define GK   1024              // K for every GEMM here

// Scratch (device globals — allocation-free rule)
__device__ float g_qh[(size_t)Mrows*HD];
__device__ float g_kh[(size_t)Mrows*HD];
__device__ float g_vh[(size_t)Mrows*HD];
__device__ float g_at[(size_t)Mrows*HD];
__device__ float g_wt[4][(size_t)GK*HD];   // transposed + tf32-rounded weights

// ===========================================================================
// helpers
// ===========================================================================
__device__ __forceinline__ uint32_t smem_u32(const void* p) {
    uint32_t a;
    asm("{ .reg .u64 t; cvta.to.shared.u64 t, %1; cvt.u32.u64 %0, t; }"
        : "=r"(a) : "l"(p));
    return a;
}

__device__ __forceinline__ uint32_t f2tf32(float x) {
    uint32_t r;
    asm("cvt.rna.tf32.f32 %0, %1;" : "=r"(r) : "f"(x));
    return r;
}

#define CP_ASYNC16(dst_u32, src_ptr) \
    asm volatile("cp.async.cg.shared.global [%0], [%1], 16;" \
                 :: "r"(dst_u32), "l"(src_ptr) : "memory")
#define CP_COMMIT() asm volatile("cp.async.commit_group;" ::: "memory")
#define CP_WAIT1()  asm volatile("cp.async.wait_group 1;" ::: "memory")
#define CP_WAIT0()  asm volatile("cp.async.wait_group 0;" ::: "memory")

__device__ __forceinline__ void mma_tf32(float* c, const uint32_t* a, const uint32_t* b) {
    asm volatile(
        "mma.sync.aligned.m16n8k8.row.col.f32.tf32.tf32.f32 "
        "{%0,%1,%2,%3}, {%4,%5,%6,%7}, {%8,%9}, {%0,%1,%2,%3};"
        : "+f"(c[0]), "+f"(c[1]), "+f"(c[2]), "+f"(c[3])
        : "r"(a[0]), "r"(a[1]), "r"(a[2]), "r"(a[3]), "r"(b[0]), "r"(b[1]));
}

// ===========================================================================
// Fused 4x transpose 1024x1024 + tf32 pre-round (weights -> K-major B)
// ===========================================================================
__global__ void __launch_bounds__(256)
transpose4(const float* __restrict__ s0, const float* __restrict__ s1,
           const float* __restrict__ s2, const float* __restrict__ s3,
           float* __restrict__ d0, float* __restrict__ d1,
           float* __restrict__ d2, float* __restrict__ d3)
{
    const float* in  = (blockIdx.z == 0) ? s0 : (blockIdx.z == 1) ? s1
                     : (blockIdx.z == 2) ? s2 : s3;
    float* out       = (blockIdx.z == 0) ? d0 : (blockIdx.z == 1) ? d1
                     : (blockIdx.z == 2) ? d2 : d3;
    __shared__ float t[32][33];
    int bx = blockIdx.x * 32, by = blockIdx.y * 32;
    #pragma unroll
    for (int i = 0; i < 32; i += 8)
        t[threadIdx.y + i][threadIdx.x] = in[(size_t)(by + threadIdx.y + i) * 1024 + bx + threadIdx.x];
    __syncthreads();
    #pragma unroll
    for (int i = 0; i < 32; i += 8)
        out[(size_t)(bx + threadIdx.y + i) * 1024 + by + threadIdx.x] =
            __uint_as_float(f2tf32(t[threadIdx.x][threadIdx.y + i]));
}

// ===========================================================================
// tf32 mma.sync GEMM: C[8192,N] = A[8192,1024] @ BT[N,1024]^T + bias
// BT pre-rounded to tf32. FUSE=1: fused per-head RMSNorm + RoPE epilogue.
// ===========================================================================
#define LDW 36
#define STG_FLOATS (128*LDW)
#define GEMM_SMEM  (4*STG_FLOATS*4)  // 73728

__device__ __forceinline__ void stage_load(uint32_t sdst, const float* __restrict__ gsrc,
                                           int tid)
{
    #pragma unroll
    for (int it = 0; it < 4; it++) {
        int idx = tid + it * 256;
        int r = idx >> 3, f = idx & 7;
        CP_ASYNC16(sdst + (r * LDW + f * 4) * 4, gsrc + (size_t)r * GK + f * 4);
    }
}

template<int FUSE>
__global__ void __launch_bounds__(256, 2)
gemm_tf32(const float* __restrict__ A, const float* __restrict__ BT,
          const float* __restrict__ bias, const float* __restrict__ rscale,
          const int* __restrict__ pos, float* __restrict__ C, int N)
{
    extern __shared__ float sm[];
    float* smA = sm;
    float* smB = sm + 2 * STG_FLOATS;
    const uint32_t sA32 = smem_u32(smA);
    const uint32_t sB32 = smem_u32(smB);

    const int tid  = threadIdx.x;
    const int wid  = tid >> 5;
    const int lane = tid & 31;
    const int g    = lane >> 2;
    const int tg   = lane & 3;
    const int wm   = wid & 3;
    const int wn   = wid >> 2;
    const int bm   = blockIdx.y, bn = blockIdx.x;

    const float* gA = A  + (size_t)(bm * 128) * GK;
    const float* gB = BT + (size_t)(bn * 128) * GK;

    float acc[2][8][4];
    #pragma unroll
    for (int mt = 0; mt < 2; mt++)
        #pragma unroll
        for (int j = 0; j < 8; j++)
            #pragma unroll
            for (int r = 0; r < 4; r++) acc[mt][j][r] = 0.f;

    const int NC = GK / 32;

    stage_load(sA32, gA + 0, tid);
    stage_load(sB32, gB + 0, tid);
    CP_COMMIT();
    stage_load(sA32 + STG_FLOATS * 4, gA + 32, tid);
    stage_load(sB32 + STG_FLOATS * 4, gB + 32, tid);
    CP_COMMIT();

    for (int c = 0; c < NC; c++) {
        if (c + 2 < NC) CP_WAIT1(); else CP_WAIT0();
        __syncthreads();

        const int s = c & 1;
        const float* as = smA + s * STG_FLOATS;
        const float* bs = smB + s * STG_FLOATS;

        #pragma unroll
        for (int ks = 0; ks < 4; ks++) {
            const int k0 = ks * 8 + tg;
            uint32_t afr[2][4], bfr[8][2];
            #pragma unroll
            for (int mt = 0; mt < 2; mt++) {
                int m0 = wm * 32 + mt * 16 + g;
                afr[mt][0] = f2tf32(as[m0 * LDW + k0]);
                afr[mt][1] = f2tf32(as[(m0 + 8) * LDW + k0]);
                afr[mt][2] = f2tf32(as[m0 * LDW + k0 + 4]);
                afr[mt][3] = f2tf32(as[(m0 + 8) * LDW + k0 + 4]);
            }
            #pragma unroll
            for (int j = 0; j < 8; j++) {
                int n0 = wn * 64 + j * 8 + g;
                bfr[j][0] = __float_as_uint(bs[n0 * LDW + k0]);       // pre-rounded
                bfr[j][1] = __float_as_uint(bs[n0 * LDW + k0 + 4]);
            }
            #pragma unroll
            for (int mt = 0; mt < 2; mt++)
                #pragma unroll
                for (int j = 0; j < 8; j++)
                    mma_tf32(acc[mt][j], afr[mt], bfr[j]);
        }
        __syncthreads();

        if (c + 2 < NC) {
            stage_load(sA32 + s * STG_FLOATS * 4, gA + (c + 2) * 32, tid);
            stage_load(sB32 + s * STG_FLOATS * 4, gB + (c + 2) * 32, tid);
            CP_COMMIT();
        }
    }

    if (FUSE == 0) {
        #pragma unroll
        for (int mt = 0; mt < 2; mt++) {
            #pragma unroll
            for (int rr = 0; rr < 2; rr++) {
                int row = bm * 128 + wm * 32 + mt * 16 + g + rr * 8;
                float* Cp = C + (size_t)row * N + bn * 128 + wn * 64;
                const float* bp = bias + bn * 128 + wn * 64;
                #pragma unroll
                for (int j = 0; j < 8; j++) {
                    int col = j * 8 + 2 * tg;
                    float2 o;
                    o.x = acc[mt][j][rr * 2 + 0] + bp[col];
                    o.y = acc[mt][j][rr * 2 + 1] + bp[col + 1];
                    *(float2*)(Cp + col) = o;
                }
            }
        }
    } else {
        // fused per-head RMSNorm + RoPE. Warp's 64 cols = one full head.
        const int hb = bn * 128 + wn * 64;       // head base column
        float bsv[8][2], scv[8][2], its[4][2];
        #pragma unroll
        for (int j = 0; j < 8; j++) {
            int hc = j * 8 + 2 * tg;
            bsv[j][0] = bias[hb + hc];     bsv[j][1] = bias[hb + hc + 1];
            scv[j][0] = 1.f + rscale[hc];  scv[j][1] = 1.f + rscale[hc + 1];
        }
        const float kfreq = -0.41523683613691915f;   // log2(10000)/32 * (-1) ... see below
        // inv timescale for i in [0,32): 10000^(-i/32) = exp2(-i * log2(10000)/32)
        #pragma unroll
        for (int j = 0; j < 4; j++) {
            int i0 = j * 8 + 2 * tg;
            its[j][0] = exp2f(kfreq * (float)i0);
            its[j][1] = exp2f(kfreq * (float)(i0 + 1));
        }
        #pragma unroll
        for (int mt = 0; mt < 2; mt++) {
            #pragma unroll
            for (int rr = 0; rr < 2; rr++) {
                int row = bm * 128 + wm * 32 + mt * 16 + g + rr * 8;
                float v[8][2], ss = 0.f;
                #pragma unroll
                for (int j = 0; j < 8; j++) {
                    v[j][0] = acc[mt][j][rr * 2 + 0] + bsv[j][0];
                    v[j][1] = acc[mt][j][rr * 2 + 1] + bsv[j][1];
                    ss += v[j][0] * v[j][0] + v[j][1] * v[j][1];
                }
                ss += __shfl_xor_sync(0xffffffffu, ss, 1);
                ss += __shfl_xor_sync(0xffffffffu, ss, 2);
                float rs = rsqrtf(ss * (1.0f / 64.0f) + 1e-6f);
                #pragma unroll
                for (int j = 0; j < 8; j++) {
                    v[j][0] *= rs * scv[j][0];
                    v[j][1] *= rs * scv[j][1];
                }
                float p = (float)pos[row];
                float* Cp = C + (size_t)row * N + hb;
                #pragma unroll
                for (int j = 0; j < 4; j++) {
                    #pragma unroll
                    for (int cc = 0; cc < 2; cc++) {
                        int i = j * 8 + 2 * tg + cc;
                        float sv, cv;
                        sincosf(p * its[j][cc], &sv, &cv);
                        float x1 = v[j][cc], x2 = v[j + 4][cc];
                        Cp[i]      = x1 * cv - x2 * sv;
                        Cp[i + 32] = x2 * cv + x1 * sv;
                    }
                }
            }
        }
    }
}

// ===========================================================================
// Flash attention with tf32 mma.sync. CTA: 128 q-rows, 8 warps (16 rows each),
// K/V tiles of 64 keys, cp.async double-buffered, smem pre-converted to tf32.
// ===========================================================================
#define LDK 68
#define LDV 72
#define KSTG (64*LDK)
#define VSTG (64*LDV)
#define FA_SMEM ((2*KSTG + 2*VSTG)*4)  // 71680 B

__global__ void __launch_bounds__(256, 2)
flash_mma(const float* __restrict__ Qx, const float* __restrict__ Kx,
          const float* __restrict__ Vx, const float* __restrict__ hs,
          float* __restrict__ O)
{
    extern __shared__ float smf[];
    float* Kbuf = smf;                // [2][64][LDK]
    float* Vbuf = smf + 2*KSTG;       // [2][64][LDV]
    const uint32_t K32 = smem_u32(Kbuf);
    const uint32_t V32 = smem_u32(Vbuf);

    const int tid  = threadIdx.x;
    const int wid  = tid >> 5;
    const int lane = tid & 31;
    const int g    = lane >> 2;
    const int t    = lane & 3;

    const int bh = blockIdx.y;
    const int b  = bh >> 4;
    const int h  = bh & 15;
    const int qt = gridDim.x - 1 - blockIdx.x;

    const size_t base = ((size_t)b * Tt * Hh + h) * QKd;
    const int row0 = qt * 128 + wid * 16;
    const int nkt  = 2 * qt + 2;

    // ---- load Q fragments once (pre-scaled by 1/8) ----
    uint32_t qa[8][4];
    {
        const float* Qp  = Qx + base + (size_t)(row0 + g) * HD;
        const float* Qp8 = Qp + (size_t)8 * HD;
        #pragma unroll
        for (int ks = 0; ks < 8; ks++) {
            int k0 = ks * 8 + t;
            qa[ks][0] = f2tf32(Qp [k0]     * 0.125f);
            qa[ks][1] = f2tf32(Qp8[k0]     * 0.125f);
            qa[ks][2] = f2tf32(Qp [k0 + 4] * 0.125f);
            qa[ks][3] = f2tf32(Qp8[k0 + 4] * 0.125f);
        }
    }

    #define LOAD_KV(kt_, s_) do {                                            \
        int tok0 = (kt_) * 64;                                               \
        uint32_t kd = K32 + (s_) * KSTG * 4;                                 \
        uint32_t vd = V32 + (s_) * VSTG * 4;                                 \
        _Pragma("unroll")                                                    \
        for (int it = 0; it < 4; it++) {                                     \
            int idx = tid + it * 256;                                        \
            int j = idx >> 4, f = (idx & 15) * 4;                            \
            const float* ksrc = Kx + base + (size_t)(tok0 + j) * HD + f;     \
            const float* vsrc = Vx + base + (size_t)(tok0 + j) * HD + f;     \
            CP_ASYNC16(kd + (j * LDK + f) * 4, ksrc);                        \
            CP_ASYNC16(vd + (j * LDV + f) * 4, vsrc);                        \
        }                                                                    \
    } while (0)

    LOAD_KV(0, 0);
    CP_COMMIT();

    float oa[8][4];
    #pragma unroll
    for (int i = 0; i < 8; i++)
        #pragma unroll
        for (int r = 0; r < 4; r++) oa[i][r] = 0.f;
    float m0 = -1e30f, m1 = -1e30f, l0 = 0.f, l1 = 0.f;

    for (int kt = 0; kt < nkt; kt++) {
        CP_WAIT0();
        __syncthreads();
        if (kt + 1 < nkt) {
            LOAD_KV(kt + 1, (kt + 1) & 1);
            CP_COMMIT();
        }
        float* Ks = Kbuf + (kt & 1) * KSTG;
        float* Vs = Vbuf + (kt & 1) * VSTG;

        // ---- one-shot tf32 conversion of the K/V tile in smem ----
        #pragma unroll
        for (int it = 0; it < 4; it++) {
            int idx = tid + it * 256;
            int j = idx >> 4, f = (idx & 15) * 4;
            float4* kp = (float4*)&Ks[j * LDK + f];
            float4 kv = *kp;
            kv.x = __uint_as_float(f2tf32(kv.x));
            kv.y = __uint_as_float(f2tf32(kv.y));
            kv.z = __uint_as_float(f2tf32(kv.z));
            kv.w = __uint_as_float(f2tf32(kv.w));
            *kp = kv;
            float4* vp = (float4*)&Vs[j * LDV + f];
            float4 vv = *vp;
            vv.x = __uint_as_float(f2tf32(vv.x));
            vv.y = __uint_as_float(f2tf32(vv.y));
            vv.z = __uint_as_float(f2tf32(vv.z));
            vv.w = __uint_as_float(f2tf32(vv.w));
            *vp = vv;
        }
        __syncthreads();

        // ---- S = Q K^T ----
        float sa[8][4];
        #pragma unroll
        for (int j = 0; j < 8; j++)
            #pragma unroll
            for (int r = 0; r < 4; r++) sa[j][r] = 0.f;

        #pragma unroll
        for (int ks = 0; ks < 8; ks++) {
            int k0 = ks * 8 + t;
            uint32_t kb[8][2];
            #pragma unroll
            for (int nj = 0; nj < 8; nj++) {
                const float* kr = Ks + (nj * 8 + g) * LDK;
                kb[nj][0] = __float_as_uint(kr[k0]);
                kb[nj][1] = __float_as_uint(kr[k0 + 4]);
            }
            #pragma unroll
            for (int nj = 0; nj < 8; nj++)
                mma_tf32(sa[nj], qa[ks], kb[nj]);
        }

        // ---- causal mask ----
        if (kt * 64 + 63 > row0) {
            int r0g = row0 + g, r1g = row0 + 8 + g;
            #pragma unroll
            for (int j = 0; j < 8; j++) {
                int c0 = kt * 64 + j * 8 + 2 * t;
                if (c0     > r0g) sa[j][0] = -1e30f;
                if (c0 + 1 > r0g) sa[j][1] = -1e30f;
                if (c0     > r1g) sa[j][2] = -1e30f;
                if (c0 + 1 > r1g) sa[j][3] = -1e30f;
            }
        }

        // ---- online softmax ----
        float rmax0 = -1e30f, rmax1 = -1e30f;
        #pragma unroll
        for (int j = 0; j < 8; j++) {
            rmax0 = fmaxf(rmax0, fmaxf(sa[j][0], sa[j][1]));
            rmax1 = fmaxf(rmax1, fmaxf(sa[j][2], sa[j][3]));
        }
        rmax0 = fmaxf(rmax0, __shfl_xor_sync(0xffffffffu, rmax0, 1));
        rmax0 = fmaxf(rmax0, __shfl_xor_sync(0xffffffffu, rmax0, 2));
        rmax1 = fmaxf(rmax1, __shfl_xor_sync(0xffffffffu, rmax1, 1));
        rmax1 = fmaxf(rmax1, __shfl_xor_sync(0xffffffffu, rmax1, 2));

        float mn0 = fmaxf(m0, rmax0), mn1 = fmaxf(m1, rmax1);
        float corr0 = __expf(m0 - mn0), corr1 = __expf(m1 - mn1);
        m0 = mn0; m1 = mn1;

        float sum0 = 0.f, sum1 = 0.f;
        #pragma unroll
        for (int j = 0; j < 8; j++) {
            sa[j][0] = __expf(sa[j][0] - mn0);
            sa[j][1] = __expf(sa[j][1] - mn0);
            sa[j][2] = __expf(sa[j][2] - mn1);
            sa[j][3] = __expf(sa[j][3] - mn1);
            sum0 += sa[j][0] + sa[j][1];
            sum1 += sa[j][2] + sa[j][3];
        }
        sum0 += __shfl_xor_sync(0xffffffffu, sum0, 1);
        sum0 += __shfl_xor_sync(0xffffffffu, sum0, 2);
        sum1 += __shfl_xor_sync(0xffffffffu, sum1, 1);
        sum1 += __shfl_xor_sync(0xffffffffu, sum1, 2);
        l0 = l0 * corr0 + sum0;
        l1 = l1 * corr1 + sum1;

        #pragma unroll
        for (int i = 0; i < 8; i++) {
            oa[i][0] *= corr0; oa[i][1] *= corr0;
            oa[i][2] *= corr1; oa[i][3] *= corr1;
        }

        // ---- O += P V (P C-layout -> A-layout via quad shuffles) ----
        const int srcA = (lane & ~3) | (t >> 1);
        const int srcB = srcA + 2;
        const bool odd = t & 1;
        #pragma unroll
        for (int js = 0; js < 8; js++) {
            float u0 = __shfl_sync(0xffffffffu, sa[js][0], srcA);
            float u1 = __shfl_sync(0xffffffffu, sa[js][1], srcA);
            float u2 = __shfl_sync(0xffffffffu, sa[js][2], srcA);
            float u3 = __shfl_sync(0xffffffffu, sa[js][3], srcA);
            float w0 = __shfl_sync(0xffffffffu, sa[js][0], srcB);
            float w1 = __shfl_sync(0xffffffffu, sa[js][1], srcB);
            float w2 = __shfl_sync(0xffffffffu, sa[js][2], srcB);
            float w3 = __shfl_sync(0xffffffffu, sa[js][3], srcB);
            uint32_t pa[4];
            pa[0] = f2tf32(odd ? u1 : u0);
            pa[1] = f2tf32(odd ? u3 : u2);
            pa[2] = f2tf32(odd ? w1 : w0);
            pa[3] = f2tf32(odd ? w3 : w2);

            const float* vr0 = Vs + (js * 8 + t) * LDV;
            const float* vr4 = Vs + (js * 8 + t + 4) * LDV;
            #pragma unroll
            for (int nt = 0; nt < 8; nt++) {
                uint32_t vb[2];
                vb[0] = __float_as_uint(vr0[nt * 8 + g]);
                vb[1] = __float_as_uint(vr4[nt * 8 + g]);
                mma_tf32(oa[nt], pa, vb);
            }
        }
        __syncthreads();
    }

    // ---- epilogue ----
    float hsc = 1.0f + hs[h];
    float inv0 = hsc / l0, inv1 = hsc / l1;
    float* O0 = O + base + (size_t)(row0 + g) * HD;
    float* O1 = O + base + (size_t)(row0 + 8 + g) * HD;
    #pragma unroll
    for (int nt = 0; nt < 8; nt++) {
        int col = nt * 8 + 2 * t;
        float2 a, c;
        a.x = oa[nt][0] * inv0; a.y = oa[nt][1] * inv0;
        c.x = oa[nt][2] * inv1; c.y = oa[nt][3] * inv1;
        *(float2*)(O0 + col) = a;
        *(float2*)(O1 + col) = c;
    }
}

// ---------------------------------------------------------------------------
// launch
// ---------------------------------------------------------------------------
extern "C" void kernel_launch(void* const* d_in, const int* in_sizes, int n_in,
                              void* d_out, int out_size)
{
    const float* q    = (const float*)d_in[0];
    const float* kv   = (const float*)d_in[1];
    const int*   qpos = (const int*)d_in[3];
    const int*   kpos = (const int*)d_in[4];
    const float* Wq   = (const float*)d_in[5];
    const float* bq   = (const float*)d_in[6];
    const float* Wk   = (const float*)d_in[7];
    const float* bk   = (const float*)d_in[8];
    const float* Wv   = (const float*)d_in[9];
    const float* bv   = (const float*)d_in[10];
    const float* qsc  = (const float*)d_in[11];
    const float* ksc  = (const float*)d_in[12];
    const float* hsc  = (const float*)d_in[13];
    const float* Wo   = (const float*)d_in[14];
    const float* bo   = (const float*)d_in[15];
    float* out = (float*)d_out;

    float *qh, *kh, *vh, *at, *wt;
    cudaGetSymbolAddress((void**)&qh, g_qh);
    cudaGetSymbolAddress((void**)&kh, g_kh);
    cudaGetSymbolAddress((void**)&vh, g_vh);
    cudaGetSymbolAddress((void**)&at, g_at);
    cudaGetSymbolAddress((void**)&wt, g_wt);
    float* WqT = wt;
    float* WkT = wt + (size_t)GK*HD;
    float* WvT = wt + 2*(size_t)GK*HD;
    float* WoT = wt + 3*(size_t)GK*HD;

    transpose4<<<dim3(32, 32, 4), dim3(32, 8)>>>(Wq, Wk, Wv, Wo, WqT, WkT, WvT, WoT);

    cudaFuncSetAttribute(gemm_tf32<0>, cudaFuncAttributeMaxDynamicSharedMemorySize, GEMM_SMEM);
    cudaFuncSetAttribute(gemm_tf32<1>, cudaFuncAttributeMaxDynamicSharedMemorySize, GEMM_SMEM);
    cudaFuncSetAttribute(flash_mma, cudaFuncAttributeMaxDynamicSharedMemorySize, FA_SMEM);

    dim3 gg(HD/128, Mrows/128);   // (8, 64)
    gemm_tf32<1><<<gg, 256, GEMM_SMEM>>>(q,  WqT, bq, qsc, qpos, qh, HD);
    gemm_tf32<1><<<gg, 256, GEMM_SMEM>>>(kv, WkT, bk, ksc, kpos, kh, HD);
    gemm_tf32<0><<<gg, 256, GEMM_SMEM>>>(kv, WvT, bv, nullptr, nullptr, vh, HD);

    flash_mma<<<dim3(Tt/128, Bq*Hh), 256, FA_SMEM>>>(qh, kh, vh, hsc, at);

    gemm_tf32<0><<<gg, 256, GEMM_SMEM>>>(at, WoT, bo, nullptr, nullptr, out, Dd);
}

// round 6
// speedup vs baseline: 3.3382x; 1.0980x over previous
#include <cuda_runtime.h>
#include <cuda_bf16.h>
#include <math.h>
#include <stdint.h>

// Problem constants
#define Bq   4
#define Tt   2048
#define Dd   1024
#define Hh   16
#define QKd  64
#define Mrows (Bq*Tt)          // 8192
#define HD   (Hh*QKd)          // 1024
#define GK   1024              // K for every GEMM here

// Scratch (device globals — allocation-free rule)
__device__ float g_qh[(size_t)Mrows*HD];
__device__ float g_kh[(size_t)Mrows*HD];
__device__ float g_vh[(size_t)Mrows*HD];
__device__ float g_at[(size_t)Mrows*HD];
__device__ float g_wt[4][(size_t)GK*HD];   // transposed + tf32-rounded weights

// ===========================================================================
// helpers
// ===========================================================================
__device__ __forceinline__ uint32_t smem_u32(const void* p) {
    uint32_t a;
    asm("{ .reg .u64 t; cvta.to.shared.u64 t, %1; cvt.u32.u64 %0, t; }"
        : "=r"(a) : "l"(p));
    return a;
}

__device__ __forceinline__ uint32_t f2tf32(float x) {
    uint32_t r;
    asm("cvt.rna.tf32.f32 %0, %1;" : "=r"(r) : "f"(x));
    return r;
}

#define CP_ASYNC16(dst_u32, src_ptr) \
    asm volatile("cp.async.cg.shared.global [%0], [%1], 16;" \
                 :: "r"(dst_u32), "l"(src_ptr) : "memory")
#define CP_COMMIT() asm volatile("cp.async.commit_group;" ::: "memory")
#define CP_WAIT1()  asm volatile("cp.async.wait_group 1;" ::: "memory")
#define CP_WAIT0()  asm volatile("cp.async.wait_group 0;" ::: "memory")

#define LDSM4(r0, r1, r2, r3, addr) \
    asm volatile("ldmatrix.sync.aligned.m8n8.x4.shared.b16 {%0,%1,%2,%3}, [%4];" \
                 : "=r"(r0), "=r"(r1), "=r"(r2), "=r"(r3) : "r"(addr))

__device__ __forceinline__ void mma_tf32(float* c, const uint32_t* a, const uint32_t* b) {
    asm volatile(
        "mma.sync.aligned.m16n8k8.row.col.f32.tf32.tf32.f32 "
        "{%0,%1,%2,%3}, {%4,%5,%6,%7}, {%8,%9}, {%0,%1,%2,%3};"
        : "+f"(c[0]), "+f"(c[1]), "+f"(c[2]), "+f"(c[3])
        : "r"(a[0]), "r"(a[1]), "r"(a[2]), "r"(a[3]), "r"(b[0]), "r"(b[1]));
}

// ===========================================================================
// Fused 4x transpose 1024x1024 + tf32 pre-round (weights -> K-major B)
// ===========================================================================
__global__ void __launch_bounds__(256)
transpose4(const float* __restrict__ s0, const float* __restrict__ s1,
           const float* __restrict__ s2, const float* __restrict__ s3,
           float* __restrict__ d0, float* __restrict__ d1,
           float* __restrict__ d2, float* __restrict__ d3)
{
    const float* in  = (blockIdx.z == 0) ? s0 : (blockIdx.z == 1) ? s1
                     : (blockIdx.z == 2) ? s2 : s3;
    float* out       = (blockIdx.z == 0) ? d0 : (blockIdx.z == 1) ? d1
                     : (blockIdx.z == 2) ? d2 : d3;
    __shared__ float t[32][33];
    int bx = blockIdx.x * 32, by = blockIdx.y * 32;
    #pragma unroll
    for (int i = 0; i < 32; i += 8)
        t[threadIdx.y + i][threadIdx.x] = in[(size_t)(by + threadIdx.y + i) * 1024 + bx + threadIdx.x];
    __syncthreads();
    #pragma unroll
    for (int i = 0; i < 32; i += 8)
        out[(size_t)(bx + threadIdx.y + i) * 1024 + by + threadIdx.x] =
            __uint_as_float(f2tf32(t[threadIdx.x][threadIdx.y + i]));
}

// ===========================================================================
// tf32 mma.sync GEMM (3-in-1): C[8192,1024] = A @ BT^T + bias
// grid.z selects problem; fuseMask bit z enables fused RMSNorm+RoPE epilogue.
// CTA 128x128, BK=32, 8 warps (4Mx2N), ldmatrix fragment loads.
// ===========================================================================
#define LDW 36
#define STG_FLOATS (128*LDW)
#define GEMM_SMEM  (4*STG_FLOATS*4)  // 73728

__device__ __forceinline__ void stage_load(uint32_t sdst, const float* __restrict__ gsrc,
                                           int tid)
{
    #pragma unroll
    for (int it = 0; it < 4; it++) {
        int idx = tid + it * 256;
        int r = idx >> 3, f = idx & 7;
        CP_ASYNC16(sdst + (r * LDW + f * 4) * 4, gsrc + (size_t)r * GK + f * 4);
    }
}

__global__ void __launch_bounds__(256, 2)
gemm3(const float* __restrict__ A0, const float* __restrict__ A1, const float* __restrict__ A2,
      const float* __restrict__ B0, const float* __restrict__ B1, const float* __restrict__ B2,
      const float* __restrict__ c0, const float* __restrict__ c1, const float* __restrict__ c2,
      const float* __restrict__ r0, const float* __restrict__ r1,
      const int* __restrict__ p0, const int* __restrict__ p1,
      float* __restrict__ C0, float* __restrict__ C1, float* __restrict__ C2,
      int fuseMask)
{
    extern __shared__ float sm[];
    float* smA = sm;
    float* smB = sm + 2 * STG_FLOATS;
    const uint32_t sA32 = smem_u32(smA);
    const uint32_t sB32 = smem_u32(smB);

    const int z = blockIdx.z;
    const float* A    = (z == 0) ? A0 : (z == 1) ? A1 : A2;
    const float* BT   = (z == 0) ? B0 : (z == 1) ? B1 : B2;
    const float* bias = (z == 0) ? c0 : (z == 1) ? c1 : c2;
    float* C          = (z == 0) ? C0 : (z == 1) ? C1 : C2;
    const float* rscale = (z == 0) ? r0 : r1;
    const int*   pos    = (z == 0) ? p0 : p1;
    const int FUSE = (fuseMask >> z) & 1;

    const int tid  = threadIdx.x;
    const int wid  = tid >> 5;
    const int lane = tid & 31;
    const int g    = lane >> 2;
    const int tg   = lane & 3;
    const int wm   = wid & 3;
    const int wn   = wid >> 2;
    const int bm   = blockIdx.y, bn = blockIdx.x;

    const float* gA = A  + (size_t)(bm * 128) * GK;
    const float* gB = BT + (size_t)(bn * 128) * GK;

    // ldmatrix per-lane offsets
    const int arow = lane & 15;                               // A: row within 16
    const int acol = (lane >> 4) << 2;                        // A: k-half
    const int brow = (lane & 7) + ((lane >> 4) << 3);         // B: row within 16
    const int bcol = ((lane >> 3) & 1) << 2;                  // B: k-half
    const uint32_t aBase = sA32 + ((wm * 32 + arow) * LDW + acol) * 4;
    const uint32_t bBase = sB32 + ((wn * 64 + brow) * LDW + bcol) * 4;

    float acc[2][8][4];
    #pragma unroll
    for (int mt = 0; mt < 2; mt++)
        #pragma unroll
        for (int j = 0; j < 8; j++)
            #pragma unroll
            for (int r = 0; r < 4; r++) acc[mt][j][r] = 0.f;

    const int NC = GK / 32;

    stage_load(sA32, gA + 0, tid);
    stage_load(sB32, gB + 0, tid);
    CP_COMMIT();
    stage_load(sA32 + STG_FLOATS * 4, gA + 32, tid);
    stage_load(sB32 + STG_FLOATS * 4, gB + 32, tid);
    CP_COMMIT();

    for (int c = 0; c < NC; c++) {
        if (c + 2 < NC) CP_WAIT1(); else CP_WAIT0();
        __syncthreads();

        const int s = c & 1;
        const uint32_t aAddr = aBase + s * STG_FLOATS * 4;
        const uint32_t bAddr = bBase + s * STG_FLOATS * 4;

        #pragma unroll
        for (int ks = 0; ks < 4; ks++) {
            const int ko = ks * 8 * 4;   // byte offset along k
            uint32_t ar[2][4], afr[2][4], bfr[8][2];
            LDSM4(ar[0][0], ar[0][1], ar[0][2], ar[0][3], aAddr + ko);
            LDSM4(ar[1][0], ar[1][1], ar[1][2], ar[1][3], aAddr + 16 * LDW * 4 + ko);
            #pragma unroll
            for (int mt = 0; mt < 2; mt++)
                #pragma unroll
                for (int i = 0; i < 4; i++)
                    afr[mt][i] = f2tf32(__uint_as_float(ar[mt][i]));

            LDSM4(bfr[0][0], bfr[0][1], bfr[1][0], bfr[1][1], bAddr + ko);
            LDSM4(bfr[2][0], bfr[2][1], bfr[3][0], bfr[3][1], bAddr + 16 * LDW * 4 + ko);
            LDSM4(bfr[4][0], bfr[4][1], bfr[5][0], bfr[5][1], bAddr + 32 * LDW * 4 + ko);
            LDSM4(bfr[6][0], bfr[6][1], bfr[7][0], bfr[7][1], bAddr + 48 * LDW * 4 + ko);

            #pragma unroll
            for (int mt = 0; mt < 2; mt++)
                #pragma unroll
                for (int j = 0; j < 8; j++)
                    mma_tf32(acc[mt][j], afr[mt], bfr[j]);
        }
        __syncthreads();

        if (c + 2 < NC) {
            stage_load(sA32 + s * STG_FLOATS * 4, gA + (c + 2) * 32, tid);
            stage_load(sB32 + s * STG_FLOATS * 4, gB + (c + 2) * 32, tid);
            CP_COMMIT();
        }
    }

    if (!FUSE) {
        #pragma unroll
        for (int mt = 0; mt < 2; mt++) {
            #pragma unroll
            for (int rr = 0; rr < 2; rr++) {
                int row = bm * 128 + wm * 32 + mt * 16 + g + rr * 8;
                float* Cp = C + (size_t)row * HD + bn * 128 + wn * 64;
                const float* bp = bias + bn * 128 + wn * 64;
                #pragma unroll
                for (int j = 0; j < 8; j++) {
                    int col = j * 8 + 2 * tg;
                    float2 o;
                    o.x = acc[mt][j][rr * 2 + 0] + bp[col];
                    o.y = acc[mt][j][rr * 2 + 1] + bp[col + 1];
                    *(float2*)(Cp + col) = o;
                }
            }
        }
    } else {
        // fused per-head RMSNorm + RoPE. Warp's 64 cols = one full head.
        const int hb = bn * 128 + wn * 64;
        float bsv[8][2], scv[8][2], its[4][2];
        #pragma unroll
        for (int j = 0; j < 8; j++) {
            int hc = j * 8 + 2 * tg;
            bsv[j][0] = bias[hb + hc];     bsv[j][1] = bias[hb + hc + 1];
            scv[j][0] = 1.f + rscale[hc];  scv[j][1] = 1.f + rscale[hc + 1];
        }
        const float kfreq = -0.41523683613691915f;  // -log2(10000)/32
        #pragma unroll
        for (int j = 0; j < 4; j++) {
            int i0 = j * 8 + 2 * tg;
            its[j][0] = exp2f(kfreq * (float)i0);
            its[j][1] = exp2f(kfreq * (float)(i0 + 1));
        }
        #pragma unroll
        for (int mt = 0; mt < 2; mt++) {
            #pragma unroll
            for (int rr = 0; rr < 2; rr++) {
                int row = bm * 128 + wm * 32 + mt * 16 + g + rr * 8;
                float v[8][2], ss = 0.f;
                #pragma unroll
                for (int j = 0; j < 8; j++) {
                    v[j][0] = acc[mt][j][rr * 2 + 0] + bsv[j][0];
                    v[j][1] = acc[mt][j][rr * 2 + 1] + bsv[j][1];
                    ss += v[j][0] * v[j][0] + v[j][1] * v[j][1];
                }
                ss += __shfl_xor_sync(0xffffffffu, ss, 1);
                ss += __shfl_xor_sync(0xffffffffu, ss, 2);
                float rs = rsqrtf(ss * (1.0f / 64.0f) + 1e-6f);
                #pragma unroll
                for (int j = 0; j < 8; j++) {
                    v[j][0] *= rs * scv[j][0];
                    v[j][1] *= rs * scv[j][1];
                }
                float p = (float)pos[row];
                float* Cp = C + (size_t)row * HD + hb;
                #pragma unroll
                for (int j = 0; j < 4; j++) {
                    #pragma unroll
                    for (int cc = 0; cc < 2; cc++) {
                        int i = j * 8 + 2 * tg + cc;
                        float sv, cv;
                        sincosf(p * its[j][cc], &sv, &cv);
                        float x1 = v[j][cc], x2 = v[j + 4][cc];
                        Cp[i]      = x1 * cv - x2 * sv;
                        Cp[i + 32] = x2 * cv + x1 * sv;
                    }
                }
            }
        }
    }
}

// ===========================================================================
// Flash attention, tf32 mma.sync, ldmatrix K-frags. 128 q-rows/CTA, 8 warps.
// ===========================================================================
#define LDK 68
#define LDV 72
#define KSTG (64*LDK)
#define VSTG (64*LDV)
#define FA_SMEM ((2*KSTG + 2*VSTG)*4)  // 71680 B

__global__ void __launch_bounds__(256, 2)
flash_mma(const float* __restrict__ Qx, const float* __restrict__ Kx,
          const float* __restrict__ Vx, const float* __restrict__ hs,
          float* __restrict__ O)
{
    extern __shared__ float smf[];
    float* Kbuf = smf;
    float* Vbuf = smf + 2*KSTG;
    const uint32_t K32 = smem_u32(Kbuf);
    const uint32_t V32 = smem_u32(Vbuf);

    const int tid  = threadIdx.x;
    const int wid  = tid >> 5;
    const int lane = tid & 31;
    const int g    = lane >> 2;
    const int t    = lane & 3;

    const int bh = blockIdx.y;
    const int b  = bh >> 4;
    const int h  = bh & 15;
    const int qt = gridDim.x - 1 - blockIdx.x;

    const size_t base = ((size_t)b * Tt * Hh + h) * QKd;
    const int row0 = qt * 128 + wid * 16;
    const int nkt  = 2 * qt + 2;

    // ldmatrix lane offsets for K B-frags
    const int brow = (lane & 7) + ((lane >> 4) << 3);
    const int bcol = ((lane >> 3) & 1) << 2;
    const uint32_t kBase = K32 + (brow * LDK + bcol) * 4;

    // ---- load Q fragments once (pre-scaled by 1/8) ----
    uint32_t qa[8][4];
    {
        const float* Qp  = Qx + base + (size_t)(row0 + g) * HD;
        const float* Qp8 = Qp + (size_t)8 * HD;
        #pragma unroll
        for (int ks = 0; ks < 8; ks++) {
            int k0 = ks * 8 + t;
            qa[ks][0] = f2tf32(Qp [k0]     * 0.125f);
            qa[ks][1] = f2tf32(Qp8[k0]     * 0.125f);
            qa[ks][2] = f2tf32(Qp [k0 + 4] * 0.125f);
            qa[ks][3] = f2tf32(Qp8[k0 + 4] * 0.125f);
        }
    }

    #define LOAD_KV(kt_, s_) do {                                            \
        int tok0 = (kt_) * 64;                                               \
        uint32_t kd = K32 + (s_) * KSTG * 4;                                 \
        uint32_t vd = V32 + (s_) * VSTG * 4;                                 \
        _Pragma("unroll")                                                    \
        for (int it = 0; it < 4; it++) {                                     \
            int idx = tid + it * 256;                                        \
            int j = idx >> 4, f = (idx & 15) * 4;                            \
            const float* ksrc = Kx + base + (size_t)(tok0 + j) * HD + f;     \
            const float* vsrc = Vx + base + (size_t)(tok0 + j) * HD + f;     \
            CP_ASYNC16(kd + (j * LDK + f) * 4, ksrc);                        \
            CP_ASYNC16(vd + (j * LDV + f) * 4, vsrc);                        \
        }                                                                    \
    } while (0)

    LOAD_KV(0, 0);
    CP_COMMIT();

    float oa[8][4];
    #pragma unroll
    for (int i = 0; i < 8; i++)
        #pragma unroll
        for (int r = 0; r < 4; r++) oa[i][r] = 0.f;
    float m0 = -1e30f, m1 = -1e30f, l0 = 0.f, l1 = 0.f;

    for (int kt = 0; kt < nkt; kt++) {
        CP_WAIT0();
        __syncthreads();
        if (kt + 1 < nkt) {
            LOAD_KV(kt + 1, (kt + 1) & 1);
            CP_COMMIT();
        }
        float* Ks = Kbuf + (kt & 1) * KSTG;
        float* Vs = Vbuf + (kt & 1) * VSTG;

        // ---- one-shot tf32 conversion of the K/V tile in smem ----
        #pragma unroll
        for (int it = 0; it < 4; it++) {
            int idx = tid + it * 256;
            int j = idx >> 4, f = (idx & 15) * 4;
            float4* kp = (float4*)&Ks[j * LDK + f];
            float4 kv = *kp;
            kv.x = __uint_as_float(f2tf32(kv.x));
            kv.y = __uint_as_float(f2tf32(kv.y));
            kv.z = __uint_as_float(f2tf32(kv.z));
            kv.w = __uint_as_float(f2tf32(kv.w));
            *kp = kv;
            float4* vp = (float4*)&Vs[j * LDV + f];
            float4 vv = *vp;
            vv.x = __uint_as_float(f2tf32(vv.x));
            vv.y = __uint_as_float(f2tf32(vv.y));
            vv.z = __uint_as_float(f2tf32(vv.z));
            vv.w = __uint_as_float(f2tf32(vv.w));
            *vp = vv;
        }
        __syncthreads();

        // ---- S = Q K^T (K B-frags via ldmatrix) ----
        float sa[8][4];
        #pragma unroll
        for (int j = 0; j < 8; j++)
            #pragma unroll
            for (int r = 0; r < 4; r++) sa[j][r] = 0.f;

        const uint32_t kAddr = kBase + (kt & 1) * KSTG * 4;
        #pragma unroll
        for (int ks = 0; ks < 8; ks++) {
            const int ko = ks * 8 * 4;
            uint32_t kb[8][2];
            LDSM4(kb[0][0], kb[0][1], kb[1][0], kb[1][1], kAddr + ko);
            LDSM4(kb[2][0], kb[2][1], kb[3][0], kb[3][1], kAddr + 16 * LDK * 4 + ko);
            LDSM4(kb[4][0], kb[4][1], kb[5][0], kb[5][1], kAddr + 32 * LDK * 4 + ko);
            LDSM4(kb[6][0], kb[6][1], kb[7][0], kb[7][1], kAddr + 48 * LDK * 4 + ko);
            #pragma unroll
            for (int nj = 0; nj < 8; nj++)
                mma_tf32(sa[nj], qa[ks], kb[nj]);
        }

        // ---- causal mask ----
        if (kt * 64 + 63 > row0) {
            int r0g = row0 + g, r1g = row0 + 8 + g;
            #pragma unroll
            for (int j = 0; j < 8; j++) {
                int c0 = kt * 64 + j * 8 + 2 * t;
                if (c0     > r0g) sa[j][0] = -1e30f;
                if (c0 + 1 > r0g) sa[j][1] = -1e30f;
                if (c0     > r1g) sa[j][2] = -1e30f;
                if (c0 + 1 > r1g) sa[j][3] = -1e30f;
            }
        }

        // ---- online softmax ----
        float rmax0 = -1e30f, rmax1 = -1e30f;
        #pragma unroll
        for (int j = 0; j < 8; j++) {
            rmax0 = fmaxf(rmax0, fmaxf(sa[j][0], sa[j][1]));
            rmax1 = fmaxf(rmax1, fmaxf(sa[j][2], sa[j][3]));
        }
        rmax0 = fmaxf(rmax0, __shfl_xor_sync(0xffffffffu, rmax0, 1));
        rmax0 = fmaxf(rmax0, __shfl_xor_sync(0xffffffffu, rmax0, 2));
        rmax1 = fmaxf(rmax1, __shfl_xor_sync(0xffffffffu, rmax1, 1));
        rmax1 = fmaxf(rmax1, __shfl_xor_sync(0xffffffffu, rmax1, 2));

        float mn0 = fmaxf(m0, rmax0), mn1 = fmaxf(m1, rmax1);
        float corr0 = __expf(m0 - mn0), corr1 = __expf(m1 - mn1);
        m0 = mn0; m1 = mn1;

        float sum0 = 0.f, sum1 = 0.f;
        #pragma unroll
        for (int j = 0; j < 8; j++) {
            sa[j][0] = __expf(sa[j][0] - mn0);
            sa[j][1] = __expf(sa[j][1] - mn0);
            sa[j][2] = __expf(sa[j][2] - mn1);
            sa[j][3] = __expf(sa[j][3] - mn1);
            sum0 += sa[j][0] + sa[j][1];
            sum1 += sa[j][2] + sa[j][3];
        }
        sum0 += __shfl_xor_sync(0xffffffffu, sum0, 1);
        sum0 += __shfl_xor_sync(0xffffffffu, sum0, 2);
        sum1 += __shfl_xor_sync(0xffffffffu, sum1, 1);
        sum1 += __shfl_xor_sync(0xffffffffu, sum1, 2);
        l0 = l0 * corr0 + sum0;
        l1 = l1 * corr1 + sum1;

        #pragma unroll
        for (int i = 0; i < 8; i++) {
            oa[i][0] *= corr0; oa[i][1] *= corr0;
            oa[i][2] *= corr1; oa[i][3] *= corr1;
        }

        // ---- O += P V (P C-layout -> A-layout via quad shuffles) ----
        const int srcA = (lane & ~3) | (t >> 1);
        const int srcB = srcA + 2;
        const bool odd = t & 1;
        #pragma unroll
        for (int js = 0; js < 8; js++) {
            float u0 = __shfl_sync(0xffffffffu, sa[js][0], srcA);
            float u1 = __shfl_sync(0xffffffffu, sa[js][1], srcA);
            float u2 = __shfl_sync(0xffffffffu, sa[js][2], srcA);
            float u3 = __shfl_sync(0xffffffffu, sa[js][3], srcA);
            float w0 = __shfl_sync(0xffffffffu, sa[js][0], srcB);
            float w1 = __shfl_sync(0xffffffffu, sa[js][1], srcB);
            float w2 = __shfl_sync(0xffffffffu, sa[js][2], srcB);
            float w3 = __shfl_sync(0xffffffffu, sa[js][3], srcB);
            uint32_t pa[4];
            pa[0] = f2tf32(odd ? u1 : u0);
            pa[1] = f2tf32(odd ? u3 : u2);
            pa[2] = f2tf32(odd ? w1 : w0);
            pa[3] = f2tf32(odd ? w3 : w2);

            const float* vr0 = Vs + (js * 8 + t) * LDV;
            const float* vr4 = Vs + (js * 8 + t + 4) * LDV;
            #pragma unroll
            for (int nt = 0; nt < 8; nt++) {
                uint32_t vb[2];
                vb[0] = __float_as_uint(vr0[nt * 8 + g]);
                vb[1] = __float_as_uint(vr4[nt * 8 + g]);
                mma_tf32(oa[nt], pa, vb);
            }
        }
        __syncthreads();
    }

    // ---- epilogue ----
    float hsc = 1.0f + hs[h];
    float inv0 = hsc / l0, inv1 = hsc / l1;
    float* O0 = O + base + (size_t)(row0 + g) * HD;
    float* O1 = O + base + (size_t)(row0 + 8 + g) * HD;
    #pragma unroll
    for (int nt = 0; nt < 8; nt++) {
        int col = nt * 8 + 2 * t;
        float2 a, c;
        a.x = oa[nt][0] * inv0; a.y = oa[nt][1] * inv0;
        c.x = oa[nt][2] * inv1; c.y = oa[nt][3] * inv1;
        *(float2*)(O0 + col) = a;
        *(float2*)(O1 + col) = c;
    }
}

// ---------------------------------------------------------------------------
// launch
// ---------------------------------------------------------------------------
extern "C" void kernel_launch(void* const* d_in, const int* in_sizes, int n_in,
                              void* d_out, int out_size)
{
    const float* q    = (const float*)d_in[0];
    const float* kv   = (const float*)d_in[1];
    const int*   qpos = (const int*)d_in[3];
    const int*   kpos = (const int*)d_in[4];
    const float* Wq   = (const float*)d_in[5];
    const float* bq   = (const float*)d_in[6];
    const float* Wk   = (const float*)d_in[7];
    const float* bk   = (const float*)d_in[8];
    const float* Wv   = (const float*)d_in[9];
    const float* bv   = (const float*)d_in[10];
    const float* qsc  = (const float*)d_in[11];
    const float* ksc  = (const float*)d_in[12];
    const float* hsc  = (const float*)d_in[13];
    const float* Wo   = (const float*)d_in[14];
    const float* bo   = (const float*)d_in[15];
    float* out = (float*)d_out;

    float *qh, *kh, *vh, *at, *wt;
    cudaGetSymbolAddress((void**)&qh, g_qh);
    cudaGetSymbolAddress((void**)&kh, g_kh);
    cudaGetSymbolAddress((void**)&vh, g_vh);
    cudaGetSymbolAddress((void**)&at, g_at);
    cudaGetSymbolAddress((void**)&wt, g_wt);
    float* WqT = wt;
    float* WkT = wt + (size_t)GK*HD;
    float* WvT = wt + 2*(size_t)GK*HD;
    float* WoT = wt + 3*(size_t)GK*HD;

    transpose4<<<dim3(32, 32, 4), dim3(32, 8)>>>(Wq, Wk, Wv, Wo, WqT, WkT, WvT, WoT);

    cudaFuncSetAttribute(gemm3, cudaFuncAttributeMaxDynamicSharedMemorySize, GEMM_SMEM);
    cudaFuncSetAttribute(flash_mma, cudaFuncAttributeMaxDynamicSharedMemorySize, FA_SMEM);

    // Q, K, V projections in one launch (z = 0,1,2)
    gemm3<<<dim3(HD/128, Mrows/128, 3), 256, GEMM_SMEM>>>(
        q, kv, kv,  WqT, WkT, WvT,  bq, bk, bv,
        qsc, ksc,  qpos, kpos,  qh, kh, vh,  0b011);

    flash_mma<<<dim3(Tt/128, Bq*Hh), 256, FA_SMEM>>>(qh, kh, vh, hsc, at);

    // O projection
    gemm3<<<dim3(HD/128, Mrows/128, 1), 256, GEMM_SMEM>>>(
        at, at, at,  WoT, WoT, WoT,  bo, bo, bo,
        qsc, ksc,  qpos, kpos,  out, out, out,  0);
}

// round 7
// speedup vs baseline: 3.5949x; 1.0769x over previous
#include <cuda_runtime.h>
#include <cuda_bf16.h>
#include <math.h>
#include <stdint.h>

// Problem constants
#define Bq   4
#define Tt   2048
#define Dd   1024
#define Hh   16
#define QKd  64
#define Mrows (Bq*Tt)          // 8192
#define HD   (Hh*QKd)          // 1024
#define GK   1024              // K for every GEMM here

// Scratch (device globals — allocation-free rule)
__device__ float g_qh[(size_t)Mrows*HD];
__device__ float g_kh[(size_t)Mrows*HD];
__device__ float g_vh[(size_t)Mrows*HD];
__device__ float g_at[(size_t)Mrows*HD];
__device__ float g_wt[4][(size_t)GK*HD];   // transposed + tf32-rounded weights

// ===========================================================================
// helpers
// ===========================================================================
__device__ __forceinline__ uint32_t smem_u32(const void* p) {
    uint32_t a;
    asm("{ .reg .u64 t; cvta.to.shared.u64 t, %1; cvt.u32.u64 %0, t; }"
        : "=r"(a) : "l"(p));
    return a;
}

__device__ __forceinline__ uint32_t f2tf32(float x) {
    uint32_t r;
    asm("cvt.rna.tf32.f32 %0, %1;" : "=r"(r) : "f"(x));
    return r;
}
__device__ __forceinline__ float f2tf32f(float x) {
    return __uint_as_float(f2tf32(x));
}

#define CP_ASYNC16(dst_u32, src_ptr) \
    asm volatile("cp.async.cg.shared.global [%0], [%1], 16;" \
                 :: "r"(dst_u32), "l"(src_ptr) : "memory")
#define CP_COMMIT() asm volatile("cp.async.commit_group;" ::: "memory")
#define CP_WAIT1()  asm volatile("cp.async.wait_group 1;" ::: "memory")
#define CP_WAIT0()  asm volatile("cp.async.wait_group 0;" ::: "memory")

#define LDSM4(r0, r1, r2, r3, addr) \
    asm volatile("ldmatrix.sync.aligned.m8n8.x4.shared.b16 {%0,%1,%2,%3}, [%4];" \
                 : "=r"(r0), "=r"(r1), "=r"(r2), "=r"(r3) : "r"(addr))

__device__ __forceinline__ void mma_tf32(float* c, const uint32_t* a, const uint32_t* b) {
    asm volatile(
        "mma.sync.aligned.m16n8k8.row.col.f32.tf32.tf32.f32 "
        "{%0,%1,%2,%3}, {%4,%5,%6,%7}, {%8,%9}, {%0,%1,%2,%3};"
        : "+f"(c[0]), "+f"(c[1]), "+f"(c[2]), "+f"(c[3])
        : "r"(a[0]), "r"(a[1]), "r"(a[2]), "r"(a[3]), "r"(b[0]), "r"(b[1]));
}

// ===========================================================================
// Fused 4x transpose 1024x1024 + tf32 pre-round (weights -> K-major B)
// ===========================================================================
__global__ void __launch_bounds__(256)
transpose4(const float* __restrict__ s0, const float* __restrict__ s1,
           const float* __restrict__ s2, const float* __restrict__ s3,
           float* __restrict__ d0, float* __restrict__ d1,
           float* __restrict__ d2, float* __restrict__ d3)
{
    const float* in  = (blockIdx.z == 0) ? s0 : (blockIdx.z == 1) ? s1
                     : (blockIdx.z == 2) ? s2 : s3;
    float* out       = (blockIdx.z == 0) ? d0 : (blockIdx.z == 1) ? d1
                     : (blockIdx.z == 2) ? d2 : d3;
    __shared__ float t[32][33];
    int bx = blockIdx.x * 32, by = blockIdx.y * 32;
    #pragma unroll
    for (int i = 0; i < 32; i += 8)
        t[threadIdx.y + i][threadIdx.x] = in[(size_t)(by + threadIdx.y + i) * 1024 + bx + threadIdx.x];
    __syncthreads();
    #pragma unroll
    for (int i = 0; i < 32; i += 8)
        out[(size_t)(bx + threadIdx.y + i) * 1024 + by + threadIdx.x] =
            f2tf32f(t[threadIdx.x][threadIdx.y + i]);
}

// ===========================================================================
// tf32 mma.sync GEMM (multi-problem): C[8192,1024] = A @ BT^T + bias
// 3-stage cp.async pipeline, ONE barrier per BK-chunk.
// PREA=1: A operand is pre-rounded tf32 (skip CVT).
// fuseMask bit z: fused RMSNorm+RoPE epilogue. roundMask bit z: tf32-round outputs.
// ===========================================================================
#define LDW 36
#define STG_FLOATS (128*LDW)                 // per operand per stage
#define STAGE_BYTES (2*STG_FLOATS*4)         // A + B, 36864
#define GEMM_SMEM  (3*STAGE_BYTES)           // 110592

__device__ __forceinline__ void stage_load(uint32_t stageBase, const float* __restrict__ gA,
                                           const float* __restrict__ gB, int tid)
{
    #pragma unroll
    for (int it = 0; it < 4; it++) {
        int idx = tid + it * 256;
        int r = idx >> 3, f = idx & 7;
        CP_ASYNC16(stageBase + (r * LDW + f * 4) * 4, gA + (size_t)r * GK + f * 4);
        CP_ASYNC16(stageBase + STG_FLOATS * 4 + (r * LDW + f * 4) * 4, gB + (size_t)r * GK + f * 4);
    }
}

template<int PREA>
__global__ void __launch_bounds__(256, 2)
gemm3(const float* __restrict__ A0, const float* __restrict__ A1, const float* __restrict__ A2,
      const float* __restrict__ B0, const float* __restrict__ B1, const float* __restrict__ B2,
      const float* __restrict__ c0, const float* __restrict__ c1, const float* __restrict__ c2,
      const float* __restrict__ r0, const float* __restrict__ r1,
      const int* __restrict__ p0, const int* __restrict__ p1,
      float* __restrict__ C0, float* __restrict__ C1, float* __restrict__ C2,
      int fuseMask, int roundMask)
{
    extern __shared__ float sm[];
    const uint32_t s32 = smem_u32(sm);

    const int z = blockIdx.z;
    const float* A    = (z == 0) ? A0 : (z == 1) ? A1 : A2;
    const float* BT   = (z == 0) ? B0 : (z == 1) ? B1 : B2;
    const float* bias = (z == 0) ? c0 : (z == 1) ? c1 : c2;
    float* C          = (z == 0) ? C0 : (z == 1) ? C1 : C2;
    const float* rscale = (z == 0) ? r0 : r1;
    const int*   pos    = (z == 0) ? p0 : p1;
    const int FUSE = (fuseMask >> z) & 1;
    const int ROUT = (roundMask >> z) & 1;

    const int tid  = threadIdx.x;
    const int wid  = tid >> 5;
    const int lane = tid & 31;
    const int g    = lane >> 2;
    const int tg   = lane & 3;
    const int wm   = wid & 3;
    const int wn   = wid >> 2;
    const int bm   = blockIdx.y, bn = blockIdx.x;

    const float* gA = A  + (size_t)(bm * 128) * GK;
    const float* gB = BT + (size_t)(bn * 128) * GK;

    // ldmatrix per-lane offsets (relative to stage base)
    const int arow = lane & 15;
    const int acol = (lane >> 4) << 2;
    const int brow = (lane & 7) + ((lane >> 4) << 3);
    const int bcol = ((lane >> 3) & 1) << 2;
    const uint32_t aOff = ((wm * 32 + arow) * LDW + acol) * 4;
    const uint32_t bOff = STG_FLOATS * 4 + ((wn * 64 + brow) * LDW + bcol) * 4;

    float acc[2][8][4];
    #pragma unroll
    for (int mt = 0; mt < 2; mt++)
        #pragma unroll
        for (int j = 0; j < 8; j++)
            #pragma unroll
            for (int r = 0; r < 4; r++) acc[mt][j][r] = 0.f;

    const int NC = GK / 32;

    stage_load(s32,               gA,      gB,      tid); CP_COMMIT();
    stage_load(s32 + STAGE_BYTES, gA + 32, gB + 32, tid); CP_COMMIT();

    int s = 0, sn = 2;   // read stage, next-load stage
    for (int c = 0; c < NC; c++) {
        if (c + 2 < NC) CP_WAIT1(); else CP_WAIT0();
        __syncthreads();

        if (c + 2 < NC) {
            stage_load(s32 + sn * STAGE_BYTES, gA + (c + 2) * 32, gB + (c + 2) * 32, tid);
            CP_COMMIT();
        }

        const uint32_t aAddr = s32 + s * STAGE_BYTES + aOff;
        const uint32_t bAddr = s32 + s * STAGE_BYTES + bOff;

        #pragma unroll
        for (int ks = 0; ks < 4; ks++) {
            const int ko = ks * 8 * 4;
            uint32_t afr[2][4], bfr[8][2];
            LDSM4(afr[0][0], afr[0][1], afr[0][2], afr[0][3], aAddr + ko);
            LDSM4(afr[1][0], afr[1][1], afr[1][2], afr[1][3], aAddr + 16 * LDW * 4 + ko);
            if (!PREA) {
                #pragma unroll
                for (int mt = 0; mt < 2; mt++)
                    #pragma unroll
                    for (int i = 0; i < 4; i++)
                        afr[mt][i] = f2tf32(__uint_as_float(afr[mt][i]));
            }
            LDSM4(bfr[0][0], bfr[0][1], bfr[1][0], bfr[1][1], bAddr + ko);
            LDSM4(bfr[2][0], bfr[2][1], bfr[3][0], bfr[3][1], bAddr + 16 * LDW * 4 + ko);
            LDSM4(bfr[4][0], bfr[4][1], bfr[5][0], bfr[5][1], bAddr + 32 * LDW * 4 + ko);
            LDSM4(bfr[6][0], bfr[6][1], bfr[7][0], bfr[7][1], bAddr + 48 * LDW * 4 + ko);

            #pragma unroll
            for (int mt = 0; mt < 2; mt++)
                #pragma unroll
                for (int j = 0; j < 8; j++)
                    mma_tf32(acc[mt][j], afr[mt], bfr[j]);
        }

        s = (s == 2) ? 0 : s + 1;
        sn = (sn == 2) ? 0 : sn + 1;
    }

    if (!FUSE) {
        #pragma unroll
        for (int mt = 0; mt < 2; mt++) {
            #pragma unroll
            for (int rr = 0; rr < 2; rr++) {
                int row = bm * 128 + wm * 32 + mt * 16 + g + rr * 8;
                float* Cp = C + (size_t)row * HD + bn * 128 + wn * 64;
                const float* bp = bias + bn * 128 + wn * 64;
                #pragma unroll
                for (int j = 0; j < 8; j++) {
                    int col = j * 8 + 2 * tg;
                    float2 o;
                    o.x = acc[mt][j][rr * 2 + 0] + bp[col];
                    o.y = acc[mt][j][rr * 2 + 1] + bp[col + 1];
                    if (ROUT) { o.x = f2tf32f(o.x); o.y = f2tf32f(o.y); }
                    *(float2*)(Cp + col) = o;
                }
            }
        }
    } else {
        // fused per-head RMSNorm + RoPE. Warp's 64 cols = one full head.
        const int hb = bn * 128 + wn * 64;
        float bsv[8][2], scv[8][2], its[4][2];
        #pragma unroll
        for (int j = 0; j < 8; j++) {
            int hc = j * 8 + 2 * tg;
            bsv[j][0] = bias[hb + hc];     bsv[j][1] = bias[hb + hc + 1];
            scv[j][0] = 1.f + rscale[hc];  scv[j][1] = 1.f + rscale[hc + 1];
        }
        const float kfreq = -0.41523683613691915f;  // -log2(10000)/32
        #pragma unroll
        for (int j = 0; j < 4; j++) {
            int i0 = j * 8 + 2 * tg;
            its[j][0] = exp2f(kfreq * (float)i0);
            its[j][1] = exp2f(kfreq * (float)(i0 + 1));
        }
        #pragma unroll
        for (int mt = 0; mt < 2; mt++) {
            #pragma unroll
            for (int rr = 0; rr < 2; rr++) {
                int row = bm * 128 + wm * 32 + mt * 16 + g + rr * 8;
                float v[8][2], ss = 0.f;
                #pragma unroll
                for (int j = 0; j < 8; j++) {
                    v[j][0] = acc[mt][j][rr * 2 + 0] + bsv[j][0];
                    v[j][1] = acc[mt][j][rr * 2 + 1] + bsv[j][1];
                    ss += v[j][0] * v[j][0] + v[j][1] * v[j][1];
                }
                ss += __shfl_xor_sync(0xffffffffu, ss, 1);
                ss += __shfl_xor_sync(0xffffffffu, ss, 2);
                float rs = rsqrtf(ss * (1.0f / 64.0f) + 1e-6f);
                #pragma unroll
                for (int j = 0; j < 8; j++) {
                    v[j][0] *= rs * scv[j][0];
                    v[j][1] *= rs * scv[j][1];
                }
                float p = (float)pos[row];
                float* Cp = C + (size_t)row * HD + hb;
                #pragma unroll
                for (int j = 0; j < 4; j++) {
                    #pragma unroll
                    for (int cc = 0; cc < 2; cc++) {
                        int i = j * 8 + 2 * tg + cc;
                        float sv, cv;
                        sincosf(p * its[j][cc], &sv, &cv);
                        float y1 = v[j][cc] * cv - v[j + 4][cc] * sv;
                        float y2 = v[j + 4][cc] * cv + v[j][cc] * sv;
                        if (ROUT) { y1 = f2tf32f(y1); y2 = f2tf32f(y2); }
                        Cp[i]      = y1;
                        Cp[i + 32] = y2;
                    }
                }
            }
        }
    }
}

// ===========================================================================
// Flash attention, tf32 mma.sync, ldmatrix K-frags. 128 q-rows/CTA, 8 warps.
// K/V arrive pre-rounded to tf32 -> no conversion pass; ONE barrier per iter.
// ===========================================================================
#define LDK 68
#define LDV 72
#define KSTG (64*LDK)
#define VSTG (64*LDV)
#define FA_SMEM ((2*KSTG + 2*VSTG)*4)  // 71680 B

__global__ void __launch_bounds__(256, 2)
flash_mma(const float* __restrict__ Qx, const float* __restrict__ Kx,
          const float* __restrict__ Vx, const float* __restrict__ hs,
          float* __restrict__ O)
{
    extern __shared__ float smf[];
    float* Kbuf = smf;
    float* Vbuf = smf + 2*KSTG;
    const uint32_t K32 = smem_u32(Kbuf);
    const uint32_t V32 = smem_u32(Vbuf);

    const int tid  = threadIdx.x;
    const int wid  = tid >> 5;
    const int lane = tid & 31;
    const int g    = lane >> 2;
    const int t    = lane & 3;

    const int bh = blockIdx.y;
    const int b  = bh >> 4;
    const int h  = bh & 15;
    const int qt = gridDim.x - 1 - blockIdx.x;

    const size_t base = ((size_t)b * Tt * Hh + h) * QKd;
    const int row0 = qt * 128 + wid * 16;
    const int nkt  = 2 * qt + 2;

    const int brow = (lane & 7) + ((lane >> 4) << 3);
    const int bcol = ((lane >> 3) & 1) << 2;
    const uint32_t kBase = K32 + (brow * LDK + bcol) * 4;

    // ---- load Q fragments once (scaled by 1/8, rounded here) ----
    uint32_t qa[8][4];
    {
        const float* Qp  = Qx + base + (size_t)(row0 + g) * HD;
        const float* Qp8 = Qp + (size_t)8 * HD;
        #pragma unroll
        for (int ks = 0; ks < 8; ks++) {
            int k0 = ks * 8 + t;
            qa[ks][0] = f2tf32(Qp [k0]     * 0.125f);
            qa[ks][1] = f2tf32(Qp8[k0]     * 0.125f);
            qa[ks][2] = f2tf32(Qp [k0 + 4] * 0.125f);
            qa[ks][3] = f2tf32(Qp8[k0 + 4] * 0.125f);
        }
    }

    #define LOAD_KV(kt_, s_) do {                                            \
        int tok0 = (kt_) * 64;                                               \
        uint32_t kd = K32 + (s_) * KSTG * 4;                                 \
        uint32_t vd = V32 + (s_) * VSTG * 4;                                 \
        _Pragma("unroll")                                                    \
        for (int it = 0; it < 4; it++) {                                     \
            int idx = tid + it * 256;                                        \
            int j = idx >> 4, f = (idx & 15) * 4;                            \
            const float* ksrc = Kx + base + (size_t)(tok0 + j) * HD + f;     \
            const float* vsrc = Vx + base + (size_t)(tok0 + j) * HD + f;     \
            CP_ASYNC16(kd + (j * LDK + f) * 4, ksrc);                        \
            CP_ASYNC16(vd + (j * LDV + f) * 4, vsrc);                        \
        }                                                                    \
    } while (0)

    LOAD_KV(0, 0);
    CP_COMMIT();

    float oa[8][4];
    #pragma unroll
    for (int i = 0; i < 8; i++)
        #pragma unroll
        for (int r = 0; r < 4; r++) oa[i][r] = 0.f;
    float m0 = -1e30f, m1 = -1e30f, l0 = 0.f, l1 = 0.f;

    for (int kt = 0; kt < nkt; kt++) {
        CP_WAIT0();
        __syncthreads();
        if (kt + 1 < nkt) {
            LOAD_KV(kt + 1, (kt + 1) & 1);
            CP_COMMIT();
        }
        const float* Vs = Vbuf + (kt & 1) * VSTG;

        // ---- S = Q K^T (K B-frags via ldmatrix, already tf32) ----
        float sa[8][4];
        #pragma unroll
        for (int j = 0; j < 8; j++)
            #pragma unroll
            for (int r = 0; r < 4; r++) sa[j][r] = 0.f;

        const uint32_t kAddr = kBase + (kt & 1) * KSTG * 4;
        #pragma unroll
        for (int ks = 0; ks < 8; ks++) {
            const int ko = ks * 8 * 4;
            uint32_t kb[8][2];
            LDSM4(kb[0][0], kb[0][1], kb[1][0], kb[1][1], kAddr + ko);
            LDSM4(kb[2][0], kb[2][1], kb[3][0], kb[3][1], kAddr + 16 * LDK * 4 + ko);
            LDSM4(kb[4][0], kb[4][1], kb[5][0], kb[5][1], kAddr + 32 * LDK * 4 + ko);
            LDSM4(kb[6][0], kb[6][1], kb[7][0], kb[7][1], kAddr + 48 * LDK * 4 + ko);
            #pragma unroll
            for (int nj = 0; nj < 8; nj++)
                mma_tf32(sa[nj], qa[ks], kb[nj]);
        }

        // ---- causal mask ----
        if (kt * 64 + 63 > row0) {
            int r0g = row0 + g, r1g = row0 + 8 + g;
            #pragma unroll
            for (int j = 0; j < 8; j++) {
                int c0 = kt * 64 + j * 8 + 2 * t;
                if (c0     > r0g) sa[j][0] = -1e30f;
                if (c0 + 1 > r0g) sa[j][1] = -1e30f;
                if (c0     > r1g) sa[j][2] = -1e30f;
                if (c0 + 1 > r1g) sa[j][3] = -1e30f;
            }
        }

        // ---- online softmax ----
        float rmax0 = -1e30f, rmax1 = -1e30f;
        #pragma unroll
        for (int j = 0; j < 8; j++) {
            rmax0 = fmaxf(rmax0, fmaxf(sa[j][0], sa[j][1]));
            rmax1 = fmaxf(rmax1, fmaxf(sa[j][2], sa[j][3]));
        }
        rmax0 = fmaxf(rmax0, __shfl_xor_sync(0xffffffffu, rmax0, 1));
        rmax0 = fmaxf(rmax0, __shfl_xor_sync(0xffffffffu, rmax0, 2));
        rmax1 = fmaxf(rmax1, __shfl_xor_sync(0xffffffffu, rmax1, 1));
        rmax1 = fmaxf(rmax1, __shfl_xor_sync(0xffffffffu, rmax1, 2));

        float mn0 = fmaxf(m0, rmax0), mn1 = fmaxf(m1, rmax1);
        float corr0 = __expf(m0 - mn0), corr1 = __expf(m1 - mn1);
        m0 = mn0; m1 = mn1;

        float sum0 = 0.f, sum1 = 0.f;
        #pragma unroll
        for (int j = 0; j < 8; j++) {
            sa[j][0] = __expf(sa[j][0] - mn0);
            sa[j][1] = __expf(sa[j][1] - mn0);
            sa[j][2] = __expf(sa[j][2] - mn1);
            sa[j][3] = __expf(sa[j][3] - mn1);
            sum0 += sa[j][0] + sa[j][1];
            sum1 += sa[j][2] + sa[j][3];
        }
        sum0 += __shfl_xor_sync(0xffffffffu, sum0, 1);
        sum0 += __shfl_xor_sync(0xffffffffu, sum0, 2);
        sum1 += __shfl_xor_sync(0xffffffffu, sum1, 1);
        sum1 += __shfl_xor_sync(0xffffffffu, sum1, 2);
        l0 = l0 * corr0 + sum0;
        l1 = l1 * corr1 + sum1;

        #pragma unroll
        for (int i = 0; i < 8; i++) {
            oa[i][0] *= corr0; oa[i][1] *= corr0;
            oa[i][2] *= corr1; oa[i][3] *= corr1;
        }

        // ---- O += P V (P C-layout -> A-layout via quad shuffles) ----
        const int srcA = (lane & ~3) | (t >> 1);
        const int srcB = srcA + 2;
        const bool odd = t & 1;
        #pragma unroll
        for (int js = 0; js < 8; js++) {
            float u0 = __shfl_sync(0xffffffffu, sa[js][0], srcA);
            float u1 = __shfl_sync(0xffffffffu, sa[js][1], srcA);
            float u2 = __shfl_sync(0xffffffffu, sa[js][2], srcA);
            float u3 = __shfl_sync(0xffffffffu, sa[js][3], srcA);
            float w0 = __shfl_sync(0xffffffffu, sa[js][0], srcB);
            float w1 = __shfl_sync(0xffffffffu, sa[js][1], srcB);
            float w2 = __shfl_sync(0xffffffffu, sa[js][2], srcB);
            float w3 = __shfl_sync(0xffffffffu, sa[js][3], srcB);
            uint32_t pa[4];
            pa[0] = f2tf32(odd ? u1 : u0);
            pa[1] = f2tf32(odd ? u3 : u2);
            pa[2] = f2tf32(odd ? w1 : w0);
            pa[3] = f2tf32(odd ? w3 : w2);

            const float* vr0 = Vs + (js * 8 + t) * LDV;
            const float* vr4 = Vs + (js * 8 + t + 4) * LDV;
            #pragma unroll
            for (int nt = 0; nt < 8; nt++) {
                uint32_t vb[2];
                vb[0] = __float_as_uint(vr0[nt * 8 + g]);
                vb[1] = __float_as_uint(vr4[nt * 8 + g]);
                mma_tf32(oa[nt], pa, vb);
            }
        }
    }

    // ---- epilogue (writes pre-rounded tf32 so O-proj can skip CVT) ----
    float hsc = 1.0f + hs[h];
    float inv0 = hsc / l0, inv1 = hsc / l1;
    float* O0 = O + base + (size_t)(row0 + g) * HD;
    float* O1 = O + base + (size_t)(row0 + 8 + g) * HD;
    #pragma unroll
    for (int nt = 0; nt < 8; nt++) {
        int col = nt * 8 + 2 * t;
        float2 a, c;
        a.x = f2tf32f(oa[nt][0] * inv0); a.y = f2tf32f(oa[nt][1] * inv0);
        c.x = f2tf32f(oa[nt][2] * inv1); c.y = f2tf32f(oa[nt][3] * inv1);
        *(float2*)(O0 + col) = a;
        *(float2*)(O1 + col) = c;
    }
}

// ---------------------------------------------------------------------------
// launch
// ---------------------------------------------------------------------------
extern "C" void kernel_launch(void* const* d_in, const int* in_sizes, int n_in,
                              void* d_out, int out_size)
{
    const float* q    = (const float*)d_in[0];
    const float* kv   = (const float*)d_in[1];
    const int*   qpos = (const int*)d_in[3];
    const int*   kpos = (const int*)d_in[4];
    const float* Wq   = (const float*)d_in[5];
    const float* bq   = (const float*)d_in[6];
    const float* Wk   = (const float*)d_in[7];
    const float* bk   = (const float*)d_in[8];
    const float* Wv   = (const float*)d_in[9];
    const float* bv   = (const float*)d_in[10];
    const float* qsc  = (const float*)d_in[11];
    const float* ksc  = (const float*)d_in[12];
    const float* hsc  = (const float*)d_in[13];
    const float* Wo   = (const float*)d_in[14];
    const float* bo   = (const float*)d_in[15];
    float* out = (float*)d_out;

    float *qh, *kh, *vh, *at, *wt;
    cudaGetSymbolAddress((void**)&qh, g_qh);
    cudaGetSymbolAddress((void**)&kh, g_kh);
    cudaGetSymbolAddress((void**)&vh, g_vh);
    cudaGetSymbolAddress((void**)&at, g_at);
    cudaGetSymbolAddress((void**)&wt, g_wt);
    float* WqT = wt;
    float* WkT = wt + (size_t)GK*HD;
    float* WvT = wt + 2*(size_t)GK*HD;
    float* WoT = wt + 3*(size_t)GK*HD;

    transpose4<<<dim3(32, 32, 4), dim3(32, 8)>>>(Wq, Wk, Wv, Wo, WqT, WkT, WvT, WoT);

    cudaFuncSetAttribute(gemm3<0>, cudaFuncAttributeMaxDynamicSharedMemorySize, GEMM_SMEM);
    cudaFuncSetAttribute(gemm3<1>, cudaFuncAttributeMaxDynamicSharedMemorySize, GEMM_SMEM);
    cudaFuncSetAttribute(flash_mma, cudaFuncAttributeMaxDynamicSharedMemorySize, FA_SMEM);

    // Q, K, V projections in one launch; K and V outputs pre-rounded to tf32.
    gemm3<0><<<dim3(HD/128, Mrows/128, 3), 256, GEMM_SMEM>>>(
        q, kv, kv,  WqT, WkT, WvT,  bq, bk, bv,
        qsc, ksc,  qpos, kpos,  qh, kh, vh,  0b011, 0b110);

    flash_mma<<<dim3(Tt/128, Bq*Hh), 256, FA_SMEM>>>(qh, kh, vh, hsc, at);

    // O projection: A (= at) is pre-rounded -> skip mainloop CVTs.
    gemm3<1><<<dim3(HD/128, Mrows/128, 1), 256, GEMM_SMEM>>>(
        at, at, at,  WoT, WoT, WoT,  bo, bo, bo,
        qsc, ksc,  qpos, kpos,  out, out, out,  0, 0);
}